// round 2
// baseline (speedup 1.0000x reference)
#include <cuda_runtime.h>
#include <math.h>
#include <math_constants.h>

#define M_ROWS 4096
#define T_LEN  2048
#define N_H    8

// ---------------- scratch (no allocations allowed) ----------------
__device__ float g_Wpack[512 * 1024];
__device__ float g_qkv[4096 * 1024];
__device__ float g_y[4096 * 512];
__device__ float g_h[4096 * 512];
__device__ float g_t1[4096 * 512];
__device__ float g_t2[4096 * 512];
__device__ float g_t3[4096 * 512];

// ---------------- weight packing: Wpack[d][n], n = [q(256) | k(256) | v(512)] ----------------
__global__ void pack_kernel(const float* __restrict__ qp, const float* __restrict__ kp,
                            const float* __restrict__ wv, float* __restrict__ Wp) {
    int idx = blockIdx.x * blockDim.x + threadIdx.x;
    if (idx >= 512 * 1024) return;
    int d = idx >> 10, n = idx & 1023;
    float v;
    if (n < 256) {
        v = qp[((n >> 5) * 512 + d) * 32 + (n & 31)];
    } else if (n < 512) {
        int nn = n - 256;
        v = kp[((nn >> 5) * 512 + d) * 32 + (nn & 31)];
    } else {
        v = wv[(n - 512) * 512 + d];   // w_v.T
    }
    Wp[idx] = v;
}

// ---------------- generic 64x64 tiled fp32 GEMM ----------------
// TRANSB=false: B is [K,N] row-major.  TRANSB=true: B is [N,K] row-major (compute A @ B^T).
// EPI: 0 = none, 1 = res + acc, 2 = res + silu(acc), 3 = tanh(acc / (softplus(extra[n])+1e-4))
template <bool TRANSB, int EPI>
__global__ void gemm64(const float* __restrict__ A, const float* __restrict__ Bm,
                       const float* __restrict__ Res, float* __restrict__ C,
                       int M, int N, int K, const float* __restrict__ extra) {
    __shared__ float As[64][16];
    __shared__ float Bs[16][64];
    int tid = threadIdx.x;
    int tx = tid & 15, ty = tid >> 4;
    int m0 = blockIdx.y * 64, n0 = blockIdx.x * 64;
    float acc[4][4] = {};

    for (int k0 = 0; k0 < K; k0 += 16) {
        {   // A tile: 64x16, one float4 per thread
            int r = tid >> 2, q = tid & 3;
            *(float4*)&As[r][q * 4] = *(const float4*)&A[(m0 + r) * K + k0 + q * 4];
        }
        if (TRANSB) {
            int n = tid >> 2, q = tid & 3;
            float4 v = make_float4(0.f, 0.f, 0.f, 0.f);
            if (n0 + n < N) v = *(const float4*)&Bm[(n0 + n) * K + k0 + q * 4];
            Bs[q * 4 + 0][n] = v.x; Bs[q * 4 + 1][n] = v.y;
            Bs[q * 4 + 2][n] = v.z; Bs[q * 4 + 3][n] = v.w;
        } else {
            int r = tid >> 4, q = tid & 15;
            *(float4*)&Bs[r][q * 4] = *(const float4*)&Bm[(k0 + r) * N + n0 + q * 4];
        }
        __syncthreads();
#pragma unroll
        for (int kk = 0; kk < 16; kk++) {
            float4 bv = *(float4*)&Bs[kk][tx * 4];
            float a0 = As[ty * 4 + 0][kk], a1 = As[ty * 4 + 1][kk];
            float a2 = As[ty * 4 + 2][kk], a3 = As[ty * 4 + 3][kk];
            acc[0][0] += a0 * bv.x; acc[0][1] += a0 * bv.y; acc[0][2] += a0 * bv.z; acc[0][3] += a0 * bv.w;
            acc[1][0] += a1 * bv.x; acc[1][1] += a1 * bv.y; acc[1][2] += a1 * bv.z; acc[1][3] += a1 * bv.w;
            acc[2][0] += a2 * bv.x; acc[2][1] += a2 * bv.y; acc[2][2] += a2 * bv.z; acc[2][3] += a2 * bv.w;
            acc[3][0] += a3 * bv.x; acc[3][1] += a3 * bv.y; acc[3][2] += a3 * bv.z; acc[3][3] += a3 * bv.w;
        }
        __syncthreads();
    }
#pragma unroll
    for (int i = 0; i < 4; i++) {
#pragma unroll
        for (int j = 0; j < 4; j++) {
            int m = m0 + ty * 4 + i;
            int n = n0 + tx * 4 + j;
            if (n >= N) continue;
            float v = acc[i][j];
            if (EPI == 1) {
                v += Res[m * N + n];
            } else if (EPI == 2) {
                float sg = 1.0f / (1.0f + expf(-v));
                v = Res[m * N + n] + v * sg;
            } else if (EPI == 3) {
                float ct = extra[n];
                float sp = (ct > 20.0f) ? ct : log1pf(expf(ct));
                v = tanhf(v / (sp + 1e-4f));
            }
            C[m * N + n] = v;
        }
    }
}

// ---------------- RoPE (+ fold q_gain * 1/sqrt(d_proj) into q) ----------------
__global__ void rope_kernel(float* __restrict__ qkv, const float* __restrict__ q_gain) {
    int idx = blockIdx.x * blockDim.x + threadIdx.x;
    if (idx >= 2 * 4096 * 8 * 16) return;
    int i = idx & 15;
    int h = (idx >> 4) & 7;
    int m = (idx >> 7) & 4095;
    int which = idx >> 19;          // 0 = q, 1 = k
    int t = m & (T_LEN - 1);

    double fd = pow(10000.0, -(double)(2 * i) / 32.0);
    float ff = (float)fd;
    float ang = (float)t * ff;      // fp32 product, matching jnp pipeline
    double ad = (double)ang;
    float c = (float)cos(ad);
    float s = (float)sin(ad);

    int col = which * 256 + h * 32;
    float x1 = qkv[m * 1024 + col + i];
    float x2 = qkv[m * 1024 + col + 16 + i];
    float o1 = x1 * c - x2 * s;
    float o2 = x2 * c + x1 * s;
    float scale = (which == 0) ? (q_gain[h] * 0.17677669529663687f) : 1.0f;
    qkv[m * 1024 + col + i]      = o1 * scale;
    qkv[m * 1024 + col + 16 + i] = o2 * scale;
}

// ---------------- causal flash attention + self-align removal ----------------
// grid (T/64, H, B), 256 threads. qkv layout: row m=b*T+t, cols [q 0:256 | k 256:512 | v 512:1024]
__global__ void attn_kernel(const float* __restrict__ qkv, float* __restrict__ y) {
    extern __shared__ float sm[];
    float* Qs = sm;                  // 64*32
    float* Ks = Qs + 64 * 32;        // 64*32
    float* Vs = Ks + 64 * 32;        // 64*64
    float* Ss = Vs + 64 * 64;        // 64*68 (padded)
    float* mrow  = Ss + 64 * 68;
    float* lrow  = mrow + 64;
    float* arow  = lrow + 64;
    float* dotrow = arow + 64;
    float* i2row  = dotrow + 64;

    int qb = blockIdx.x, h = blockIdx.y, b = blockIdx.z;
    int tid = threadIdx.x;
    int tx = tid & 15, ty = tid >> 4;
    int q0 = qb * 64;
    const float* base = qkv + (size_t)b * T_LEN * 1024;

    for (int i = tid; i < 64 * 8; i += 256) {
        int r = i >> 3, c = i & 7;
        *(float4*)&Qs[r * 32 + c * 4] = *(const float4*)&base[(q0 + r) * 1024 + h * 32 + c * 4];
    }
    if (tid < 64) { mrow[tid] = -CUDART_INF_F; lrow[tid] = 0.f; }
    float O[4][4] = {};
    __syncthreads();

    for (int j = 0; j <= qb; j++) {
        int k0 = j * 64;
        for (int i = tid; i < 64 * 8; i += 256) {
            int r = i >> 3, c = i & 7;
            *(float4*)&Ks[r * 32 + c * 4] = *(const float4*)&base[(k0 + r) * 1024 + 256 + h * 32 + c * 4];
        }
        for (int i = tid; i < 64 * 16; i += 256) {
            int r = i >> 4, c = i & 15;
            *(float4*)&Vs[r * 64 + c * 4] = *(const float4*)&base[(k0 + r) * 1024 + 512 + h * 64 + c * 4];
        }
        __syncthreads();

        float s[4][4] = {};
#pragma unroll
        for (int o = 0; o < 32; o++) {
            float qv[4], kv[4];
#pragma unroll
            for (int i = 0; i < 4; i++) qv[i] = Qs[(ty * 4 + i) * 32 + o];
#pragma unroll
            for (int jj = 0; jj < 4; jj++) kv[jj] = Ks[(tx * 4 + jj) * 32 + o];
#pragma unroll
            for (int i = 0; i < 4; i++)
#pragma unroll
                for (int jj = 0; jj < 4; jj++) s[i][jj] += qv[i] * kv[jj];
        }
        if (j == qb) {
#pragma unroll
            for (int i = 0; i < 4; i++)
#pragma unroll
                for (int jj = 0; jj < 4; jj++)
                    if (tx * 4 + jj > ty * 4 + i) s[i][jj] = -1e30f;
        }
#pragma unroll
        for (int i = 0; i < 4; i++)
#pragma unroll
            for (int jj = 0; jj < 4; jj++)
                Ss[(ty * 4 + i) * 68 + tx * 4 + jj] = s[i][jj];
        __syncthreads();

        if (tid < 64) {
            float mo = mrow[tid], mx = mo;
            float* srow = &Ss[tid * 68];
            for (int c = 0; c < 64; c++) mx = fmaxf(mx, srow[c]);
            float alpha = expf(mo - mx);
            float sum = 0.f;
            for (int c = 0; c < 64; c++) {
                float p = expf(srow[c] - mx);
                srow[c] = p;
                sum += p;
            }
            lrow[tid] = lrow[tid] * alpha + sum;
            mrow[tid] = mx;
            arow[tid] = alpha;
        }
        __syncthreads();

        float al[4];
#pragma unroll
        for (int i = 0; i < 4; i++) al[i] = arow[ty * 4 + i];
#pragma unroll
        for (int i = 0; i < 4; i++)
#pragma unroll
            for (int jj = 0; jj < 4; jj++) O[i][jj] *= al[i];
#pragma unroll
        for (int kk = 0; kk < 64; kk++) {
            float p[4];
#pragma unroll
            for (int i = 0; i < 4; i++) p[i] = Ss[(ty * 4 + i) * 68 + kk];
            float4 vv = *(float4*)&Vs[kk * 64 + tx * 4];
#pragma unroll
            for (int i = 0; i < 4; i++) {
                O[i][0] += p[i] * vv.x; O[i][1] += p[i] * vv.y;
                O[i][2] += p[i] * vv.z; O[i][3] += p[i] * vv.w;
            }
        }
        __syncthreads();
    }

    // epilogue: Vs still holds the diagonal (query-row) V tile
    if (tid < 64) {
        float ss = 0.f;
        for (int c = 0; c < 64; c++) { float v = Vs[tid * 64 + c]; ss += v * v; }
        i2row[tid] = 1.0f / fmaxf(ss, 1e-24f);
        dotrow[tid] = 0.f;
    }
    __syncthreads();
#pragma unroll
    for (int i = 0; i < 4; i++) {
        float4 vv = *(float4*)&Vs[(ty * 4 + i) * 64 + tx * 4];
        float part = O[i][0] * vv.x + O[i][1] * vv.y + O[i][2] * vv.z + O[i][3] * vv.w;
        atomicAdd(&dotrow[ty * 4 + i], part);
    }
    __syncthreads();
#pragma unroll
    for (int i = 0; i < 4; i++) {
        int q = ty * 4 + i;
        float linv = 1.0f / lrow[q];
        float coef = dotrow[q] * i2row[q];
        float4 vv = *(float4*)&Vs[q * 64 + tx * 4];
        float4 outv;
        outv.x = (O[i][0] - coef * vv.x) * linv;
        outv.y = (O[i][1] - coef * vv.y) * linv;
        outv.z = (O[i][2] - coef * vv.z) * linv;
        outv.w = (O[i][3] - coef * vv.w) * linv;
        int gidx = (b * T_LEN + q0 + q) * 512 + h * 64 + tx * 4;
        *(float4*)&y[gidx] = outv;
    }
}

// ---------------- layernorm: one warp per row of 512 ----------------
__global__ void ln_kernel(const float* __restrict__ in, const float* __restrict__ g,
                          const float* __restrict__ bta, float* __restrict__ out) {
    int row = blockIdx.x * 8 + (threadIdx.x >> 5);
    int lane = threadIdx.x & 31;
    const float* p = in + row * 512;
    float v[16];
    float s = 0.f;
#pragma unroll
    for (int j = 0; j < 16; j++) { v[j] = p[lane + 32 * j]; s += v[j]; }
#pragma unroll
    for (int off = 16; off; off >>= 1) s += __shfl_xor_sync(0xffffffffu, s, off);
    float mean = s * (1.0f / 512.0f);
    float s2 = 0.f;
#pragma unroll
    for (int j = 0; j < 16; j++) { float d = v[j] - mean; s2 += d * d; }
#pragma unroll
    for (int off = 16; off; off >>= 1) s2 += __shfl_xor_sync(0xffffffffu, s2, off);
    float r = rsqrtf(s2 * (1.0f / 512.0f) + 1e-5f);
#pragma unroll
    for (int j = 0; j < 16; j++) {
        int c = lane + 32 * j;
        out[row * 512 + c] = (v[j] - mean) * r * g[c] + bta[c];
    }
}

// ---------------- RMS norm ----------------
__global__ void rms_kernel(const float* __restrict__ in, float* __restrict__ out) {
    int row = blockIdx.x * 8 + (threadIdx.x >> 5);
    int lane = threadIdx.x & 31;
    const float* p = in + row * 512;
    float v[16];
    float s2 = 0.f;
#pragma unroll
    for (int j = 0; j < 16; j++) { v[j] = p[lane + 32 * j]; s2 += v[j] * v[j]; }
#pragma unroll
    for (int off = 16; off; off >>= 1) s2 += __shfl_xor_sync(0xffffffffu, s2, off);
    float r = rsqrtf(s2 * (1.0f / 512.0f) + 1e-6f);
#pragma unroll
    for (int j = 0; j < 16; j++) out[row * 512 + lane + 32 * j] = v[j] * r;
}

// ---------------- launch ----------------
extern "C" void kernel_launch(void* const* d_in, const int* in_sizes, int n_in,
                              void* d_out, int out_size) {
    const float* x      = (const float*)d_in[0];
    const float* qp     = (const float*)d_in[1];
    const float* kp     = (const float*)d_in[2];
    const float* wv     = (const float*)d_in[3];
    const float* wproj  = (const float*)d_in[4];
    const float* qg     = (const float*)d_in[5];
    const float* ew0    = (const float*)d_in[6];
    const float* g1     = (const float*)d_in[7];
    const float* b1     = (const float*)d_in[8];
    const float* ew1    = (const float*)d_in[9];
    const float* g2     = (const float*)d_in[10];
    const float* b2     = (const float*)d_in[11];
    const float* ew2    = (const float*)d_in[12];
    const float* ewout  = (const float*)d_in[13];
    const float* ctemp  = (const float*)d_in[14];
    float* out = (float*)d_out;

    float *Wp, *qkv, *yb, *hb, *t1, *t2, *t3;
    cudaGetSymbolAddress((void**)&Wp,  g_Wpack);
    cudaGetSymbolAddress((void**)&qkv, g_qkv);
    cudaGetSymbolAddress((void**)&yb,  g_y);
    cudaGetSymbolAddress((void**)&hb,  g_h);
    cudaGetSymbolAddress((void**)&t1,  g_t1);
    cudaGetSymbolAddress((void**)&t2,  g_t2);
    cudaGetSymbolAddress((void**)&t3,  g_t3);

    cudaFuncSetAttribute(attn_kernel, cudaFuncAttributeMaxDynamicSharedMemorySize, 52 * 1024);

    // 1. pack weights, QKV GEMM
    pack_kernel<<<(512 * 1024 + 255) / 256, 256>>>(qp, kp, wv, Wp);
    gemm64<false, 0><<<dim3(16, 64), 256>>>(x, Wp, nullptr, qkv, 4096, 1024, 512, nullptr);
    // 2. RoPE + gain/scale fold
    rope_kernel<<<4096, 256>>>(qkv, qg);
    // 3. flash attention + self-align
    attn_kernel<<<dim3(32, 8, 2), 256, 51456>>>(qkv, yb);
    // 4. h = x + y @ w_proj^T
    gemm64<true, 1><<<dim3(8, 64), 256>>>(yb, wproj, x, hb, 4096, 512, 512, nullptr);
    // 5. encoder
    gemm64<true, 0><<<dim3(8, 64), 256>>>(hb, ew0, nullptr, t1, 4096, 512, 512, nullptr);
    ln_kernel<<<512, 256>>>(t1, g1, b1, t2);
    gemm64<true, 2><<<dim3(8, 64), 256>>>(t2, ew1, hb, t3, 4096, 512, 512, nullptr);   // he1 = h + silu(...)
    ln_kernel<<<512, 256>>>(t3, g2, b2, t1);
    gemm64<true, 2><<<dim3(8, 64), 256>>>(t1, ew2, t3, t2, 4096, 512, 512, nullptr);   // he2 = he1 + silu(...)
    // 6. RMS + output head
    rms_kernel<<<512, 256>>>(t2, t1);
    gemm64<true, 3><<<dim3(1, 64), 256>>>(t1, ewout, nullptr, out, 4096, 32, 512, ctemp);
}

// round 3
// speedup vs baseline: 1.3958x; 1.3958x over previous
#include <cuda_runtime.h>
#include <math.h>
#include <math_constants.h>

#define T_LEN  2048

// ---------------- scratch (no allocations allowed) ----------------
__device__ float g_Wpack[512 * 1024];
__device__ float g_qkv[4096 * 1024];
__device__ float g_y[4096 * 512];
__device__ float g_h[4096 * 512];
__device__ float g_t1[4096 * 512];
__device__ float g_t2[4096 * 512];
__device__ float g_t3[4096 * 512];

// ---------------- weight packing: Wpack[d][n], n = [q(256) | k(256) | v(512)] ----------------
__global__ void pack_kernel(const float* __restrict__ qp, const float* __restrict__ kp,
                            const float* __restrict__ wv, float* __restrict__ Wp) {
    int idx = blockIdx.x * blockDim.x + threadIdx.x;
    if (idx >= 512 * 1024) return;
    int d = idx >> 10, n = idx & 1023;
    float v;
    if (n < 256) {
        v = qp[((n >> 5) * 512 + d) * 32 + (n & 31)];
    } else if (n < 512) {
        int nn = n - 256;
        v = kp[((nn >> 5) * 512 + d) * 32 + (nn & 31)];
    } else {
        v = wv[(n - 512) * 512 + d];   // w_v.T
    }
    Wp[idx] = v;
}

// ---------------- 128x64 tiled fp32 GEMM, 8x4 microtile ----------------
// TRANSB=false: B is [K,N] row-major.  TRANSB=true: B is [N,K] row-major (A @ B^T).
// EPI: 0 none, 1 res+acc, 2 res+silu(acc), 3 tanh(acc/(softplus(extra[n])+1e-4))
template <bool TRANSB, int EPI>
__global__ void __launch_bounds__(256, 3)
gemm128(const float* __restrict__ A, const float* __restrict__ Bm,
        const float* __restrict__ Res, float* __restrict__ C,
        int M, int N, int K, const float* __restrict__ extra) {
    __shared__ float As[16][128];   // k-major
    __shared__ float Bs[16][64];    // k-major
    int tid = threadIdx.x;
    int tx = tid & 15, ty = tid >> 4;       // tx: 16 col groups x4, ty: 16 row groups x8
    int m0 = blockIdx.y * 128, n0 = blockIdx.x * 64;
    float acc[8][4] = {};

    int ar = tid >> 1;              // A load: row 0..127
    int ak = (tid & 1) * 8;        // k offset 0 or 8

    for (int k0 = 0; k0 < K; k0 += 16) {
        // A tile 128x16 -> transposed store
        {
            const float* ap = &A[(m0 + ar) * K + k0 + ak];
            float4 v0 = *(const float4*)ap;
            float4 v1 = *(const float4*)(ap + 4);
            As[ak + 0][ar] = v0.x; As[ak + 1][ar] = v0.y;
            As[ak + 2][ar] = v0.z; As[ak + 3][ar] = v0.w;
            As[ak + 4][ar] = v1.x; As[ak + 5][ar] = v1.y;
            As[ak + 6][ar] = v1.z; As[ak + 7][ar] = v1.w;
        }
        if (TRANSB) {
            int n = tid >> 2, q = tid & 3;
            float4 v = make_float4(0.f, 0.f, 0.f, 0.f);
            if (n0 + n < N) v = *(const float4*)&Bm[(n0 + n) * K + k0 + q * 4];
            Bs[q * 4 + 0][n] = v.x; Bs[q * 4 + 1][n] = v.y;
            Bs[q * 4 + 2][n] = v.z; Bs[q * 4 + 3][n] = v.w;
        } else {
            int kk = tid >> 4, nq = tid & 15;
            *(float4*)&Bs[kk][nq * 4] = *(const float4*)&Bm[(k0 + kk) * N + n0 + nq * 4];
        }
        __syncthreads();
#pragma unroll
        for (int kk = 0; kk < 16; kk++) {
            float4 b4 = *(float4*)&Bs[kk][tx * 4];
            float4 a0 = *(float4*)&As[kk][ty * 8];
            float4 a1 = *(float4*)&As[kk][ty * 8 + 4];
            float av[8] = {a0.x, a0.y, a0.z, a0.w, a1.x, a1.y, a1.z, a1.w};
#pragma unroll
            for (int i = 0; i < 8; i++) {
                acc[i][0] += av[i] * b4.x; acc[i][1] += av[i] * b4.y;
                acc[i][2] += av[i] * b4.z; acc[i][3] += av[i] * b4.w;
            }
        }
        __syncthreads();
    }
#pragma unroll
    for (int i = 0; i < 8; i++) {
        int m = m0 + ty * 8 + i;
#pragma unroll
        for (int j = 0; j < 4; j++) {
            int n = n0 + tx * 4 + j;
            if (n >= N) continue;
            float v = acc[i][j];
            if (EPI == 1) {
                v += Res[m * N + n];
            } else if (EPI == 2) {
                float sg = 1.0f / (1.0f + __expf(-v));
                v = Res[m * N + n] + v * sg;
            } else if (EPI == 3) {
                float ct = extra[n];
                float sp = (ct > 20.0f) ? ct : log1pf(__expf(ct));
                v = tanhf(v / (sp + 1e-4f));
            }
            C[m * N + n] = v;
        }
    }
}

// ---------------- RoPE (+ fold q_gain * 1/sqrt(d_proj) into q) ----------------
__global__ void rope_kernel(float* __restrict__ qkv, const float* __restrict__ q_gain) {
    int idx = blockIdx.x * blockDim.x + threadIdx.x;
    if (idx >= 2 * 4096 * 8 * 16) return;
    int i = idx & 15;
    int h = (idx >> 4) & 7;
    int m = (idx >> 7) & 4095;
    int which = idx >> 19;          // 0 = q, 1 = k
    int t = m & (T_LEN - 1);

    double fd = pow(10000.0, -(double)(2 * i) / 32.0);
    float ff = (float)fd;
    float ang = (float)t * ff;      // fp32 product, matching jnp pipeline
    double ad = (double)ang;
    float c = (float)cos(ad);
    float s = (float)sin(ad);

    int col = which * 256 + h * 32;
    float x1 = qkv[m * 1024 + col + i];
    float x2 = qkv[m * 1024 + col + 16 + i];
    float o1 = x1 * c - x2 * s;
    float o2 = x2 * c + x1 * s;
    float scale = (which == 0) ? (q_gain[h] * 0.17677669529663687f) : 1.0f;
    qkv[m * 1024 + col + i]      = o1 * scale;
    qkv[m * 1024 + col + 16 + i] = o2 * scale;
}

// ---------------- causal flash attention + self-align removal ----------------
// grid (T/64, H, B), 256 threads. qkv row m=b*T+t, cols [q 0:256 | k 256:512 | v 512:1024]
__global__ void __launch_bounds__(256, 3) attn_kernel(const float* __restrict__ qkv,
                                                      float* __restrict__ y) {
    extern __shared__ float sm[];
    float* QsT = sm;                 // [32][64]  (dim-major, transposed)
    float* KsT = QsT + 32 * 64;      // [32][64]
    float* Vs  = KsT + 32 * 64;      // [64][64]  (row-major)
    float* Ss  = Vs + 64 * 64;       // [64][68]

    int qb = (int)gridDim.x - 1 - (int)blockIdx.x;   // big blocks first
    int h = blockIdx.y, b = blockIdx.z;
    int tid = threadIdx.x;
    int tx = tid & 15, ty = tid >> 4;
    int q0 = qb * 64;
    const float* base = qkv + (size_t)b * T_LEN * 1024;

    // load Q transposed
    for (int i = tid; i < 64 * 8; i += 256) {
        int r = i >> 3, c = i & 7;
        float4 v = *(const float4*)&base[(q0 + r) * 1024 + h * 32 + c * 4];
        QsT[(c * 4 + 0) * 64 + r] = v.x;
        QsT[(c * 4 + 1) * 64 + r] = v.y;
        QsT[(c * 4 + 2) * 64 + r] = v.z;
        QsT[(c * 4 + 3) * 64 + r] = v.w;
    }
    float m[4], l[4];
#pragma unroll
    for (int i = 0; i < 4; i++) { m[i] = -CUDART_INF_F; l[i] = 0.f; }
    float O[4][4] = {};

    for (int j = 0; j <= qb; j++) {
        int k0 = j * 64;
        // K transposed, V row-major
        for (int i = tid; i < 64 * 8; i += 256) {
            int r = i >> 3, c = i & 7;
            float4 v = *(const float4*)&base[(k0 + r) * 1024 + 256 + h * 32 + c * 4];
            KsT[(c * 4 + 0) * 64 + r] = v.x;
            KsT[(c * 4 + 1) * 64 + r] = v.y;
            KsT[(c * 4 + 2) * 64 + r] = v.z;
            KsT[(c * 4 + 3) * 64 + r] = v.w;
        }
        for (int i = tid; i < 64 * 16; i += 256) {
            int r = i >> 4, c = i & 15;
            *(float4*)&Vs[r * 64 + c * 4] = *(const float4*)&base[(k0 + r) * 1024 + 512 + h * 64 + c * 4];
        }
        __syncthreads();

        // S = Q K^T  (conflict-free: Q broadcast, K spans 64 consecutive floats)
        float s[4][4] = {};
#pragma unroll
        for (int o = 0; o < 32; o++) {
            float4 qv = *(float4*)&QsT[o * 64 + ty * 4];
            float4 kv = *(float4*)&KsT[o * 64 + tx * 4];
            s[0][0] += qv.x * kv.x; s[0][1] += qv.x * kv.y; s[0][2] += qv.x * kv.z; s[0][3] += qv.x * kv.w;
            s[1][0] += qv.y * kv.x; s[1][1] += qv.y * kv.y; s[1][2] += qv.y * kv.z; s[1][3] += qv.y * kv.w;
            s[2][0] += qv.z * kv.x; s[2][1] += qv.z * kv.y; s[2][2] += qv.z * kv.z; s[2][3] += qv.z * kv.w;
            s[3][0] += qv.w * kv.x; s[3][1] += qv.w * kv.y; s[3][2] += qv.w * kv.z; s[3][3] += qv.w * kv.w;
        }
        if (j == qb) {
#pragma unroll
            for (int i = 0; i < 4; i++)
#pragma unroll
                for (int jj = 0; jj < 4; jj++)
                    if (tx * 4 + jj > ty * 4 + i) s[i][jj] = -1e30f;
        }

        // register softmax: reductions over the 16 tx lanes (shfl_xor <= 8 stays in-half)
#pragma unroll
        for (int i = 0; i < 4; i++) {
            float tm = fmaxf(fmaxf(s[i][0], s[i][1]), fmaxf(s[i][2], s[i][3]));
#pragma unroll
            for (int d = 8; d; d >>= 1) tm = fmaxf(tm, __shfl_xor_sync(0xffffffffu, tm, d));
            float mx = fmaxf(m[i], tm);
            float alpha = __expf(m[i] - mx);
            float sum = 0.f;
#pragma unroll
            for (int jj = 0; jj < 4; jj++) { s[i][jj] = __expf(s[i][jj] - mx); sum += s[i][jj]; }
#pragma unroll
            for (int d = 8; d; d >>= 1) sum += __shfl_xor_sync(0xffffffffu, sum, d);
            l[i] = l[i] * alpha + sum;
            m[i] = mx;
            O[i][0] *= alpha; O[i][1] *= alpha; O[i][2] *= alpha; O[i][3] *= alpha;
            *(float4*)&Ss[(ty * 4 + i) * 68 + tx * 4] = make_float4(s[i][0], s[i][1], s[i][2], s[i][3]);
        }
        __syncthreads();

        // O += P V
#pragma unroll 4
        for (int kk0 = 0; kk0 < 64; kk0 += 4) {
            float p[4][4];
#pragma unroll
            for (int i = 0; i < 4; i++)
                *(float4*)p[i] = *(float4*)&Ss[(ty * 4 + i) * 68 + kk0];
#pragma unroll
            for (int u = 0; u < 4; u++) {
                float4 vv = *(float4*)&Vs[(kk0 + u) * 64 + tx * 4];
#pragma unroll
                for (int i = 0; i < 4; i++) {
                    O[i][0] += p[i][u] * vv.x; O[i][1] += p[i][u] * vv.y;
                    O[i][2] += p[i][u] * vv.z; O[i][3] += p[i][u] * vv.w;
                }
            }
        }
        __syncthreads();
    }

    // epilogue: Vs holds the diagonal tile; remove projection on v, normalize by l
#pragma unroll
    for (int i = 0; i < 4; i++) {
        int q = ty * 4 + i;
        float4 vv = *(float4*)&Vs[q * 64 + tx * 4];
        float dp = O[i][0] * vv.x + O[i][1] * vv.y + O[i][2] * vv.z + O[i][3] * vv.w;
        float nn = vv.x * vv.x + vv.y * vv.y + vv.z * vv.z + vv.w * vv.w;
#pragma unroll
        for (int d = 8; d; d >>= 1) {
            dp += __shfl_xor_sync(0xffffffffu, dp, d);
            nn += __shfl_xor_sync(0xffffffffu, nn, d);
        }
        float coef = dp / fmaxf(nn, 1e-24f);
        float linv = 1.0f / l[i];
        float4 outv;
        outv.x = (O[i][0] - coef * vv.x) * linv;
        outv.y = (O[i][1] - coef * vv.y) * linv;
        outv.z = (O[i][2] - coef * vv.z) * linv;
        outv.w = (O[i][3] - coef * vv.w) * linv;
        int gidx = (b * T_LEN + q0 + q) * 512 + h * 64 + tx * 4;
        *(float4*)&y[gidx] = outv;
    }
}

// ---------------- layernorm: one warp per row of 512 ----------------
__global__ void ln_kernel(const float* __restrict__ in, const float* __restrict__ g,
                          const float* __restrict__ bta, float* __restrict__ out) {
    int row = blockIdx.x * 8 + (threadIdx.x >> 5);
    int lane = threadIdx.x & 31;
    const float* p = in + row * 512;
    float v[16];
    float s = 0.f;
#pragma unroll
    for (int j = 0; j < 16; j++) { v[j] = p[lane + 32 * j]; s += v[j]; }
#pragma unroll
    for (int off = 16; off; off >>= 1) s += __shfl_xor_sync(0xffffffffu, s, off);
    float mean = s * (1.0f / 512.0f);
    float s2 = 0.f;
#pragma unroll
    for (int j = 0; j < 16; j++) { float d = v[j] - mean; s2 += d * d; }
#pragma unroll
    for (int off = 16; off; off >>= 1) s2 += __shfl_xor_sync(0xffffffffu, s2, off);
    float r = rsqrtf(s2 * (1.0f / 512.0f) + 1e-5f);
#pragma unroll
    for (int j = 0; j < 16; j++) {
        int c = lane + 32 * j;
        out[row * 512 + c] = (v[j] - mean) * r * g[c] + bta[c];
    }
}

// ---------------- RMS norm ----------------
__global__ void rms_kernel(const float* __restrict__ in, float* __restrict__ out) {
    int row = blockIdx.x * 8 + (threadIdx.x >> 5);
    int lane = threadIdx.x & 31;
    const float* p = in + row * 512;
    float v[16];
    float s2 = 0.f;
#pragma unroll
    for (int j = 0; j < 16; j++) { v[j] = p[lane + 32 * j]; s2 += v[j] * v[j]; }
#pragma unroll
    for (int off = 16; off; off >>= 1) s2 += __shfl_xor_sync(0xffffffffu, s2, off);
    float r = rsqrtf(s2 * (1.0f / 512.0f) + 1e-6f);
#pragma unroll
    for (int j = 0; j < 16; j++) out[row * 512 + lane + 32 * j] = v[j] * r;
}

// ---------------- launch ----------------
extern "C" void kernel_launch(void* const* d_in, const int* in_sizes, int n_in,
                              void* d_out, int out_size) {
    const float* x      = (const float*)d_in[0];
    const float* qp     = (const float*)d_in[1];
    const float* kp     = (const float*)d_in[2];
    const float* wv     = (const float*)d_in[3];
    const float* wproj  = (const float*)d_in[4];
    const float* qg     = (const float*)d_in[5];
    const float* ew0    = (const float*)d_in[6];
    const float* g1     = (const float*)d_in[7];
    const float* b1     = (const float*)d_in[8];
    const float* ew1    = (const float*)d_in[9];
    const float* g2     = (const float*)d_in[10];
    const float* b2     = (const float*)d_in[11];
    const float* ew2    = (const float*)d_in[12];
    const float* ewout  = (const float*)d_in[13];
    const float* ctemp  = (const float*)d_in[14];
    float* out = (float*)d_out;

    float *Wp, *qkv, *yb, *hb, *t1, *t2, *t3;
    cudaGetSymbolAddress((void**)&Wp,  g_Wpack);
    cudaGetSymbolAddress((void**)&qkv, g_qkv);
    cudaGetSymbolAddress((void**)&yb,  g_y);
    cudaGetSymbolAddress((void**)&hb,  g_h);
    cudaGetSymbolAddress((void**)&t1,  g_t1);
    cudaGetSymbolAddress((void**)&t2,  g_t2);
    cudaGetSymbolAddress((void**)&t3,  g_t3);

    cudaFuncSetAttribute(attn_kernel, cudaFuncAttributeMaxDynamicSharedMemorySize, 52 * 1024);

    // 1. pack weights, QKV GEMM
    pack_kernel<<<(512 * 1024 + 255) / 256, 256>>>(qp, kp, wv, Wp);
    gemm128<false, 0><<<dim3(16, 32), 256>>>(x, Wp, nullptr, qkv, 4096, 1024, 512, nullptr);
    // 2. RoPE + gain/scale fold
    rope_kernel<<<4096, 256>>>(qkv, qg);
    // 3. flash attention + self-align
    attn_kernel<<<dim3(32, 8, 2), 256, (32*64 + 32*64 + 64*64 + 64*68) * 4>>>(qkv, yb);
    // 4. h = x + y @ w_proj^T
    gemm128<true, 1><<<dim3(8, 32), 256>>>(yb, wproj, x, hb, 4096, 512, 512, nullptr);
    // 5. encoder
    gemm128<true, 0><<<dim3(8, 32), 256>>>(hb, ew0, nullptr, t1, 4096, 512, 512, nullptr);
    ln_kernel<<<512, 256>>>(t1, g1, b1, t2);
    gemm128<true, 2><<<dim3(8, 32), 256>>>(t2, ew1, hb, t3, 4096, 512, 512, nullptr);   // he1 = h + silu(...)
    ln_kernel<<<512, 256>>>(t3, g2, b2, t1);
    gemm128<true, 2><<<dim3(8, 32), 256>>>(t1, ew2, t3, t2, 4096, 512, 512, nullptr);   // he2 = he1 + silu(...)
    // 6. RMS + output head
    rms_kernel<<<512, 256>>>(t2, t1);
    gemm128<true, 3><<<dim3(1, 32), 256>>>(t1, ewout, nullptr, out, 4096, 32, 512, ctemp);
}

// round 7
// speedup vs baseline: 1.5613x; 1.1186x over previous
#include <cuda_runtime.h>
#include <cuda_bf16.h>
#include <math.h>
#include <math_constants.h>
#include <cstdint>

#define T_LEN 2048

// ---------------- scratch (no allocations allowed) ----------------
__device__ float g_qkv[4096 * 1024];
__device__ float g_h [4096 * 512];
__device__ float g_t1[4096 * 512];
__device__ float g_t2[4096 * 512];
__device__ float g_t3[4096 * 512];
__device__ __nv_bfloat16 g_A0h[4096 * 512], g_A0l[4096 * 512];
__device__ __nv_bfloat16 g_A1h[4096 * 512], g_A1l[4096 * 512];
// weight rows: [0:1024) qkv | [1024:1536) wproj | [1536:2048) ew0 | [2048:2560) ew1 | [2560:3072) ew2 | [3072:3104) ewout
__device__ __nv_bfloat16 g_Wh[3104 * 512], g_Wl[3104 * 512];

// ---------------- helpers ----------------
static __device__ __forceinline__ uint32_t smem_u32(const void* p) {
    uint32_t a;
    asm("{ .reg .u64 t; cvta.to.shared.u64 t, %1; cvt.u32.u64 %0, t; }" : "=r"(a) : "l"(p));
    return a;
}
static __device__ __forceinline__ void hilo(float v, __nv_bfloat16& h, __nv_bfloat16& l) {
    h = __float2bfloat16(v);
    l = __float2bfloat16(v - __bfloat162float(h));
}

#define LDSM_X4(r, a)                                                          \
    asm volatile("ldmatrix.sync.aligned.m8n8.x4.shared.b16 {%0,%1,%2,%3}, [%4];" \
        : "=r"((r)[0]), "=r"((r)[1]), "=r"((r)[2]), "=r"((r)[3]) : "r"(a))
#define LDSM_X2(r, a)                                                          \
    asm volatile("ldmatrix.sync.aligned.m8n8.x2.shared.b16 {%0,%1}, [%2];"     \
        : "=r"((r)[0]), "=r"((r)[1]) : "r"(a))
#define MMA_BF16(d, A, B)                                                      \
    asm volatile("mma.sync.aligned.m16n8k16.row.col.f32.bf16.bf16.f32 "        \
        "{%0,%1,%2,%3}, {%4,%5,%6,%7}, {%8,%9}, {%0,%1,%2,%3};"                \
        : "+f"((d)[0]), "+f"((d)[1]), "+f"((d)[2]), "+f"((d)[3])               \
        : "r"((A)[0]), "r"((A)[1]), "r"((A)[2]), "r"((A)[3]),                  \
          "r"((B)[0]), "r"((B)[1]))

// ---------------- weight prep ----------------
__global__ void pack_qkv(const float* __restrict__ qp, const float* __restrict__ kp,
                         const float* __restrict__ wv,
                         __nv_bfloat16* __restrict__ hi, __nv_bfloat16* __restrict__ lo) {
    int idx = blockIdx.x * blockDim.x + threadIdx.x;
    if (idx >= 1024 * 512) return;
    int n = idx >> 9, d = idx & 511;
    float v;
    if (n < 256) {
        v = qp[((n >> 5) * 512 + d) * 32 + (n & 31)];
    } else if (n < 512) {
        int nn = n - 256;
        v = kp[((nn >> 5) * 512 + d) * 32 + (nn & 31)];
    } else {
        v = wv[(size_t)(n - 512) * 512 + d];
    }
    hilo(v, hi[idx], lo[idx]);
}

__global__ void conv_hilo(const float* __restrict__ in, __nv_bfloat16* __restrict__ hi,
                          __nv_bfloat16* __restrict__ lo, int n) {
    int i = blockIdx.x * blockDim.x + threadIdx.x;
    if (i >= n) return;
    hilo(in[i], hi[i], lo[i]);
}

// ---------------- HMMA bf16x3 GEMM: D[m][n] = sum_k A[m][k]*B[n][k], K=512 ----------------
// CTA tile 128x128, 8 warps (2m x 4n), warp tile 64x32, m16n8k16 fragments.
// EPI: 0 none, 1 res+acc, 2 res+silu(acc), 3 tanh(acc/(softplus(extra[n])+1e-4))
#define PAD 72
#define GEMM_SMEM (4 * 128 * PAD * 2)
template <int EPI, bool HILO>
__global__ void __launch_bounds__(256, 2) mma_gemm(
    const __nv_bfloat16* __restrict__ Ah, const __nv_bfloat16* __restrict__ Al,
    const __nv_bfloat16* __restrict__ Bh, const __nv_bfloat16* __restrict__ Bl,
    const float* __restrict__ Res, float* __restrict__ C,
    int Ntot, int NtotB, const float* __restrict__ extra,
    __nv_bfloat16* __restrict__ Oh, __nv_bfloat16* __restrict__ Ol)
{
    extern __shared__ __nv_bfloat16 smb[];
    __nv_bfloat16* sAh = smb;                    // [128][PAD]
    __nv_bfloat16* sAl = sAh + 128 * PAD;
    __nv_bfloat16* sBh = sAl + 128 * PAD;
    __nv_bfloat16* sBl = sBh + 128 * PAD;

    int tid = threadIdx.x, lane = tid & 31, wid = tid >> 5;
    int warp_m = wid & 1, warp_n = wid >> 1;
    int m0 = blockIdx.y * 128, n0 = blockIdx.x * 128;

    uint32_t uAh = smem_u32(sAh), uAl = smem_u32(sAl);
    uint32_t uBh = smem_u32(sBh), uBl = smem_u32(sBl);

    // ldmatrix lane->address mapping
    uint32_t a_row = warp_m * 64 + (lane & 15);
    uint32_t a_ko  = (lane >> 4) * 8;
    uint32_t b_row = warp_n * 32 + (lane & 7);
    uint32_t b_ko  = ((lane >> 3) & 1) * 8;

    float acc[4][4][4] = {};

    for (int c = 0; c < 8; c++) {
        int k0c = c * 64;
        for (int i = tid; i < 1024; i += 256) {
            int r = i >> 3, q = i & 7;
            int so = r * PAD + q * 8;
            size_t g = (size_t)(m0 + r) * 512 + k0c + q * 8;
            *(float4*)(sAh + so) = *(const float4*)(Ah + g);
            *(float4*)(sAl + so) = *(const float4*)(Al + g);
        }
        for (int i = tid; i < 1024; i += 256) {
            int r = i >> 3, q = i & 7;
            int so = r * PAD + q * 8;
            int n = n0 + r;
            float4 vh = make_float4(0.f, 0.f, 0.f, 0.f), vl = vh;
            if (n < NtotB) {
                size_t g = (size_t)n * 512 + k0c + q * 8;
                vh = *(const float4*)(Bh + g);
                vl = *(const float4*)(Bl + g);
            }
            *(float4*)(sBh + so) = vh;
            *(float4*)(sBl + so) = vl;
        }
        __syncthreads();

#pragma unroll
        for (int kk = 0; kk < 4; kk++) {
            uint32_t bh[4][2], bl[4][2];
#pragma unroll
            for (int ni = 0; ni < 4; ni++) {
                uint32_t off = ((b_row + ni * 8) * PAD + kk * 16 + b_ko) * 2;
                LDSM_X2(bh[ni], uBh + off);
                LDSM_X2(bl[ni], uBl + off);
            }
#pragma unroll
            for (int mi = 0; mi < 4; mi++) {
                uint32_t ah[4], al[4];
                uint32_t off = ((a_row + mi * 16) * PAD + kk * 16 + a_ko) * 2;
                LDSM_X4(ah, uAh + off);
                LDSM_X4(al, uAl + off);
#pragma unroll
                for (int ni = 0; ni < 4; ni++) {
                    MMA_BF16(acc[mi][ni], ah, bh[ni]);
                    MMA_BF16(acc[mi][ni], ah, bl[ni]);
                    MMA_BF16(acc[mi][ni], al, bh[ni]);
                }
            }
        }
        __syncthreads();
    }

    // epilogue
    int gid = lane >> 2, tig = lane & 3;
#pragma unroll
    for (int mi = 0; mi < 4; mi++) {
#pragma unroll
        for (int ni = 0; ni < 4; ni++) {
#pragma unroll
            for (int half = 0; half < 2; half++) {
                int m = m0 + warp_m * 64 + mi * 16 + gid + half * 8;
                int nbase = n0 + warp_n * 32 + ni * 8 + tig * 2;
#pragma unroll
                for (int e = 0; e < 2; e++) {
                    int n = nbase + e;
                    if (n >= Ntot) continue;
                    float v = acc[mi][ni][half * 2 + e];
                    if (EPI == 1) {
                        v += Res[(size_t)m * Ntot + n];
                    } else if (EPI == 2) {
                        float sg = 1.0f / (1.0f + __expf(-v));
                        v = Res[(size_t)m * Ntot + n] + v * sg;
                    } else if (EPI == 3) {
                        float ct = extra[n];
                        float sp = (ct > 20.0f) ? ct : log1pf(__expf(ct));
                        v = tanhf(v / (sp + 1e-4f));
                    }
                    C[(size_t)m * Ntot + n] = v;
                    if (HILO) {
                        __nv_bfloat16 hx, lx;
                        hilo(v, hx, lx);
                        Oh[(size_t)m * 512 + n] = hx;
                        Ol[(size_t)m * 512 + n] = lx;
                    }
                }
            }
        }
    }
}

// ---------------- RoPE (+ fold q_gain * 1/sqrt(d_proj) into q) ----------------
__global__ void rope_kernel(float* __restrict__ qkv, const float* __restrict__ q_gain) {
    int idx = blockIdx.x * blockDim.x + threadIdx.x;
    if (idx >= 2 * 4096 * 8 * 16) return;
    int i = idx & 15;
    int h = (idx >> 4) & 7;
    int m = (idx >> 7) & 4095;
    int which = idx >> 19;          // 0 = q, 1 = k
    int t = m & (T_LEN - 1);

    double fd = pow(10000.0, -(double)(2 * i) / 32.0);
    float ff = (float)fd;
    float ang = (float)t * ff;
    double ad = (double)ang;
    float c = (float)cos(ad);
    float s = (float)sin(ad);

    int col = which * 256 + h * 32;
    float x1 = qkv[m * 1024 + col + i];
    float x2 = qkv[m * 1024 + col + 16 + i];
    float o1 = x1 * c - x2 * s;
    float o2 = x2 * c + x1 * s;
    float scale = (which == 0) ? (q_gain[h] * 0.17677669529663687f) : 1.0f;
    qkv[m * 1024 + col + i]      = o1 * scale;
    qkv[m * 1024 + col + 16 + i] = o2 * scale;
}

// ---------------- causal flash attention + self-align; writes bf16 hi/lo ----------------
__global__ void __launch_bounds__(256, 3) attn_kernel(const float* __restrict__ qkv,
                                                      __nv_bfloat16* __restrict__ yh,
                                                      __nv_bfloat16* __restrict__ yl) {
    extern __shared__ float sm[];
    float* QsT = sm;                 // [32][64]
    float* KsT = QsT + 32 * 64;      // [32][64]
    float* Vs  = KsT + 32 * 64;      // [64][64]
    float* Ss  = Vs + 64 * 64;       // [64][68]

    int qb = (int)gridDim.x - 1 - (int)blockIdx.x;
    int h = blockIdx.y, b = blockIdx.z;
    int tid = threadIdx.x;
    int tx = tid & 15, ty = tid >> 4;
    int q0 = qb * 64;
    const float* base = qkv + (size_t)b * T_LEN * 1024;

    for (int i = tid; i < 64 * 8; i += 256) {
        int r = i >> 3, c = i & 7;
        float4 v = *(const float4*)&base[(q0 + r) * 1024 + h * 32 + c * 4];
        QsT[(c * 4 + 0) * 64 + r] = v.x;
        QsT[(c * 4 + 1) * 64 + r] = v.y;
        QsT[(c * 4 + 2) * 64 + r] = v.z;
        QsT[(c * 4 + 3) * 64 + r] = v.w;
    }
    float m[4], l[4];
#pragma unroll
    for (int i = 0; i < 4; i++) { m[i] = -CUDART_INF_F; l[i] = 0.f; }
    float O[4][4] = {};

    for (int j = 0; j <= qb; j++) {
        int k0 = j * 64;
        for (int i = tid; i < 64 * 8; i += 256) {
            int r = i >> 3, c = i & 7;
            float4 v = *(const float4*)&base[(k0 + r) * 1024 + 256 + h * 32 + c * 4];
            KsT[(c * 4 + 0) * 64 + r] = v.x;
            KsT[(c * 4 + 1) * 64 + r] = v.y;
            KsT[(c * 4 + 2) * 64 + r] = v.z;
            KsT[(c * 4 + 3) * 64 + r] = v.w;
        }
        for (int i = tid; i < 64 * 16; i += 256) {
            int r = i >> 4, c = i & 15;
            *(float4*)&Vs[r * 64 + c * 4] = *(const float4*)&base[(k0 + r) * 1024 + 512 + h * 64 + c * 4];
        }
        __syncthreads();

        float s[4][4] = {};
#pragma unroll
        for (int o = 0; o < 32; o++) {
            float4 qv = *(float4*)&QsT[o * 64 + ty * 4];
            float4 kv = *(float4*)&KsT[o * 64 + tx * 4];
            s[0][0] += qv.x * kv.x; s[0][1] += qv.x * kv.y; s[0][2] += qv.x * kv.z; s[0][3] += qv.x * kv.w;
            s[1][0] += qv.y * kv.x; s[1][1] += qv.y * kv.y; s[1][2] += qv.y * kv.z; s[1][3] += qv.y * kv.w;
            s[2][0] += qv.z * kv.x; s[2][1] += qv.z * kv.y; s[2][2] += qv.z * kv.z; s[2][3] += qv.z * kv.w;
            s[3][0] += qv.w * kv.x; s[3][1] += qv.w * kv.y; s[3][2] += qv.w * kv.z; s[3][3] += qv.w * kv.w;
        }
        if (j == qb) {
#pragma unroll
            for (int i = 0; i < 4; i++)
#pragma unroll
                for (int jj = 0; jj < 4; jj++)
                    if (tx * 4 + jj > ty * 4 + i) s[i][jj] = -1e30f;
        }

#pragma unroll
        for (int i = 0; i < 4; i++) {
            float tm = fmaxf(fmaxf(s[i][0], s[i][1]), fmaxf(s[i][2], s[i][3]));
#pragma unroll
            for (int d = 8; d; d >>= 1) tm = fmaxf(tm, __shfl_xor_sync(0xffffffffu, tm, d));
            float mx = fmaxf(m[i], tm);
            float alpha = __expf(m[i] - mx);
            float sum = 0.f;
#pragma unroll
            for (int jj = 0; jj < 4; jj++) { s[i][jj] = __expf(s[i][jj] - mx); sum += s[i][jj]; }
#pragma unroll
            for (int d = 8; d; d >>= 1) sum += __shfl_xor_sync(0xffffffffu, sum, d);
            l[i] = l[i] * alpha + sum;
            m[i] = mx;
            O[i][0] *= alpha; O[i][1] *= alpha; O[i][2] *= alpha; O[i][3] *= alpha;
            *(float4*)&Ss[(ty * 4 + i) * 68 + tx * 4] = make_float4(s[i][0], s[i][1], s[i][2], s[i][3]);
        }
        __syncthreads();

#pragma unroll 4
        for (int kk0 = 0; kk0 < 64; kk0 += 4) {
            float p[4][4];
#pragma unroll
            for (int i = 0; i < 4; i++)
                *(float4*)p[i] = *(float4*)&Ss[(ty * 4 + i) * 68 + kk0];
#pragma unroll
            for (int u = 0; u < 4; u++) {
                float4 vv = *(float4*)&Vs[(kk0 + u) * 64 + tx * 4];
#pragma unroll
                for (int i = 0; i < 4; i++) {
                    O[i][0] += p[i][u] * vv.x; O[i][1] += p[i][u] * vv.y;
                    O[i][2] += p[i][u] * vv.z; O[i][3] += p[i][u] * vv.w;
                }
            }
        }
        __syncthreads();
    }

#pragma unroll
    for (int i = 0; i < 4; i++) {
        int q = ty * 4 + i;
        float4 vv = *(float4*)&Vs[q * 64 + tx * 4];
        float dp = O[i][0] * vv.x + O[i][1] * vv.y + O[i][2] * vv.z + O[i][3] * vv.w;
        float nn = vv.x * vv.x + vv.y * vv.y + vv.z * vv.z + vv.w * vv.w;
#pragma unroll
        for (int d = 8; d; d >>= 1) {
            dp += __shfl_xor_sync(0xffffffffu, dp, d);
            nn += __shfl_xor_sync(0xffffffffu, nn, d);
        }
        float coef = dp / fmaxf(nn, 1e-24f);
        float linv = 1.0f / l[i];
        float ov[4];
        ov[0] = (O[i][0] - coef * vv.x) * linv;
        ov[1] = (O[i][1] - coef * vv.y) * linv;
        ov[2] = (O[i][2] - coef * vv.z) * linv;
        ov[3] = (O[i][3] - coef * vv.w) * linv;
        size_t gidx = (size_t)(b * T_LEN + q0 + q) * 512 + h * 64 + tx * 4;
#pragma unroll
        for (int u = 0; u < 4; u++) {
            __nv_bfloat16 hx, lx;
            hilo(ov[u], hx, lx);
            yh[gidx + u] = hx;
            yl[gidx + u] = lx;
        }
    }
}

// ---------------- layernorm -> bf16 hi/lo ----------------
__global__ void ln_hilo(const float* __restrict__ in, const float* __restrict__ g,
                        const float* __restrict__ bta,
                        __nv_bfloat16* __restrict__ oh, __nv_bfloat16* __restrict__ ol) {
    int row = blockIdx.x * 8 + (threadIdx.x >> 5);
    int lane = threadIdx.x & 31;
    const float* p = in + (size_t)row * 512;
    float v[16];
    float s = 0.f;
#pragma unroll
    for (int j = 0; j < 16; j++) { v[j] = p[lane + 32 * j]; s += v[j]; }
#pragma unroll
    for (int off = 16; off; off >>= 1) s += __shfl_xor_sync(0xffffffffu, s, off);
    float mean = s * (1.0f / 512.0f);
    float s2 = 0.f;
#pragma unroll
    for (int j = 0; j < 16; j++) { float d = v[j] - mean; s2 += d * d; }
#pragma unroll
    for (int off = 16; off; off >>= 1) s2 += __shfl_xor_sync(0xffffffffu, s2, off);
    float r = rsqrtf(s2 * (1.0f / 512.0f) + 1e-5f);
#pragma unroll
    for (int j = 0; j < 16; j++) {
        int c = lane + 32 * j;
        float o = (v[j] - mean) * r * g[c] + bta[c];
        __nv_bfloat16 hx, lx;
        hilo(o, hx, lx);
        oh[(size_t)row * 512 + c] = hx;
        ol[(size_t)row * 512 + c] = lx;
    }
}

// ---------------- RMS norm -> bf16 hi/lo ----------------
__global__ void rms_hilo(const float* __restrict__ in,
                         __nv_bfloat16* __restrict__ oh, __nv_bfloat16* __restrict__ ol) {
    int row = blockIdx.x * 8 + (threadIdx.x >> 5);
    int lane = threadIdx.x & 31;
    const float* p = in + (size_t)row * 512;
    float v[16];
    float s2 = 0.f;
#pragma unroll
    for (int j = 0; j < 16; j++) { v[j] = p[lane + 32 * j]; s2 += v[j] * v[j]; }
#pragma unroll
    for (int off = 16; off; off >>= 1) s2 += __shfl_xor_sync(0xffffffffu, s2, off);
    float r = rsqrtf(s2 * (1.0f / 512.0f) + 1e-6f);
#pragma unroll
    for (int j = 0; j < 16; j++) {
        float o = v[j] * r;
        __nv_bfloat16 hx, lx;
        hilo(o, hx, lx);
        oh[(size_t)row * 512 + lane + 32 * j] = hx;
        ol[(size_t)row * 512 + lane + 32 * j] = lx;
    }
}

// ---------------- launch ----------------
extern "C" void kernel_launch(void* const* d_in, const int* in_sizes, int n_in,
                              void* d_out, int out_size) {
    const float* x      = (const float*)d_in[0];
    const float* qp     = (const float*)d_in[1];
    const float* kp     = (const float*)d_in[2];
    const float* wv     = (const float*)d_in[3];
    const float* wproj  = (const float*)d_in[4];
    const float* qg     = (const float*)d_in[5];
    const float* ew0    = (const float*)d_in[6];
    const float* g1     = (const float*)d_in[7];
    const float* b1     = (const float*)d_in[8];
    const float* ew1    = (const float*)d_in[9];
    const float* g2     = (const float*)d_in[10];
    const float* b2     = (const float*)d_in[11];
    const float* ew2    = (const float*)d_in[12];
    const float* ewout  = (const float*)d_in[13];
    const float* ctemp  = (const float*)d_in[14];
    float* out = (float*)d_out;

    float *qkv, *hb, *t1, *t2, *t3;
    __nv_bfloat16 *A0h, *A0l, *A1h, *A1l, *Wh, *Wl;
    cudaGetSymbolAddress((void**)&qkv, g_qkv);
    cudaGetSymbolAddress((void**)&hb,  g_h);
    cudaGetSymbolAddress((void**)&t1,  g_t1);
    cudaGetSymbolAddress((void**)&t2,  g_t2);
    cudaGetSymbolAddress((void**)&t3,  g_t3);
    cudaGetSymbolAddress((void**)&A0h, g_A0h);
    cudaGetSymbolAddress((void**)&A0l, g_A0l);
    cudaGetSymbolAddress((void**)&A1h, g_A1h);
    cudaGetSymbolAddress((void**)&A1l, g_A1l);
    cudaGetSymbolAddress((void**)&Wh,  g_Wh);
    cudaGetSymbolAddress((void**)&Wl,  g_Wl);

    cudaFuncSetAttribute(attn_kernel, cudaFuncAttributeMaxDynamicSharedMemorySize, 52 * 1024);
    cudaFuncSetAttribute(mma_gemm<0, false>, cudaFuncAttributeMaxDynamicSharedMemorySize, GEMM_SMEM);
    cudaFuncSetAttribute(mma_gemm<1, true >, cudaFuncAttributeMaxDynamicSharedMemorySize, GEMM_SMEM);
    cudaFuncSetAttribute(mma_gemm<2, false>, cudaFuncAttributeMaxDynamicSharedMemorySize, GEMM_SMEM);
    cudaFuncSetAttribute(mma_gemm<3, false>, cudaFuncAttributeMaxDynamicSharedMemorySize, GEMM_SMEM);

    // weight prep (independent, up-front)
    pack_qkv<<<2048, 256>>>(qp, kp, wv, Wh, Wl);
    conv_hilo<<<1024, 256>>>(wproj, Wh + 1024 * 512, Wl + 1024 * 512, 512 * 512);
    conv_hilo<<<1024, 256>>>(ew0,   Wh + 1536 * 512, Wl + 1536 * 512, 512 * 512);
    conv_hilo<<<1024, 256>>>(ew1,   Wh + 2048 * 512, Wl + 2048 * 512, 512 * 512);
    conv_hilo<<<1024, 256>>>(ew2,   Wh + 2560 * 512, Wl + 2560 * 512, 512 * 512);
    conv_hilo<<<64,   256>>>(ewout, Wh + 3072 * 512, Wl + 3072 * 512, 32 * 512);
    conv_hilo<<<8192, 256>>>(x, A0h, A0l, 4096 * 512);

    // 1. QKV
    mma_gemm<0, false><<<dim3(8, 32), 256, GEMM_SMEM>>>(A0h, A0l, Wh, Wl, nullptr, qkv,
                                                        1024, 1024, nullptr, nullptr, nullptr);
    // 2. RoPE
    rope_kernel<<<4096, 256>>>(qkv, qg);
    // 3. attention -> A1 (bf16 hi/lo)
    attn_kernel<<<dim3(32, 8, 2), 256, (32*64 + 32*64 + 64*64 + 64*68) * 4>>>(qkv, A1h, A1l);
    // 4. h = x + y @ wproj^T  (+ hilo of h -> A0)
    mma_gemm<1, true><<<dim3(4, 32), 256, GEMM_SMEM>>>(A1h, A1l, Wh + 1024 * 512, Wl + 1024 * 512,
                                                       x, hb, 512, 512, nullptr, A0h, A0l);
    // 5. t1 = h @ ew0^T
    mma_gemm<0, false><<<dim3(4, 32), 256, GEMM_SMEM>>>(A0h, A0l, Wh + 1536 * 512, Wl + 1536 * 512,
                                                        nullptr, t1, 512, 512, nullptr, nullptr, nullptr);
    ln_hilo<<<512, 256>>>(t1, g1, b1, A1h, A1l);
    // 6. t3 = h + silu(ln1 @ ew1^T)
    mma_gemm<2, false><<<dim3(4, 32), 256, GEMM_SMEM>>>(A1h, A1l, Wh + 2048 * 512, Wl + 2048 * 512,
                                                        hb, t3, 512, 512, nullptr, nullptr, nullptr);
    ln_hilo<<<512, 256>>>(t3, g2, b2, A0h, A0l);
    // 7. t2 = t3 + silu(ln2 @ ew2^T)
    mma_gemm<2, false><<<dim3(4, 32), 256, GEMM_SMEM>>>(A0h, A0l, Wh + 2560 * 512, Wl + 2560 * 512,
                                                        t3, t2, 512, 512, nullptr, nullptr, nullptr);
    // 8. rms + head
    rms_hilo<<<512, 256>>>(t2, A1h, A1l);
    mma_gemm<3, false><<<dim3(1, 32), 256, GEMM_SMEM>>>(A1h, A1l, Wh + 3072 * 512, Wl + 3072 * 512,
                                                        nullptr, out, 32, 32, ctemp, nullptr, nullptr);
}

// round 9
// speedup vs baseline: 2.0920x; 1.3399x over previous
#include <cuda_runtime.h>
#include <cuda_bf16.h>
#include <math.h>
#include <math_constants.h>
#include <cstdint>

#define T_LEN 2048

// ---------------- scratch (no allocations allowed) ----------------
__device__ float g_qkv[4096 * 1024];
__device__ float g_h [4096 * 512];
__device__ float g_t1[4096 * 512];
__device__ float g_t2[4096 * 512];
__device__ float g_t3[4096 * 512];
__device__ __nv_bfloat16 g_A0h[4096 * 512], g_A0l[4096 * 512];
__device__ __nv_bfloat16 g_A1h[4096 * 512], g_A1l[4096 * 512];
__device__ __nv_bfloat16 g_Qh[4096 * 256], g_Ql[4096 * 256];
__device__ __nv_bfloat16 g_Kh[4096 * 256], g_Kl[4096 * 256];
__device__ __nv_bfloat16 g_Vh[4096 * 512], g_Vl[4096 * 512];
// weight rows: [0:1024) qkv | [1024:1536) wproj | [1536:2048) ew0 | [2048:2560) ew1 | [2560:3072) ew2 | [3072:3104) ewout
__device__ __nv_bfloat16 g_Wh[3104 * 512], g_Wl[3104 * 512];

// ---------------- helpers ----------------
static __device__ __forceinline__ uint32_t smem_u32(const void* p) {
    uint32_t a;
    asm("{ .reg .u64 t; cvta.to.shared.u64 t, %1; cvt.u32.u64 %0, t; }" : "=r"(a) : "l"(p));
    return a;
}
static __device__ __forceinline__ void hilo(float v, __nv_bfloat16& h, __nv_bfloat16& l) {
    h = __float2bfloat16(v);
    l = __float2bfloat16(v - __bfloat162float(h));
}
static __device__ __forceinline__ void packhl(float a, float b, uint32_t& ph, uint32_t& pl) {
    __nv_bfloat162 hp, lp;
    hp.x = __float2bfloat16(a);
    hp.y = __float2bfloat16(b);
    lp.x = __float2bfloat16(a - __bfloat162float(hp.x));
    lp.y = __float2bfloat16(b - __bfloat162float(hp.y));
    ph = *(uint32_t*)&hp;
    pl = *(uint32_t*)&lp;
}

#define LDSM_X4(r, a)                                                          \
    asm volatile("ldmatrix.sync.aligned.m8n8.x4.shared.b16 {%0,%1,%2,%3}, [%4];" \
        : "=r"((r)[0]), "=r"((r)[1]), "=r"((r)[2]), "=r"((r)[3]) : "r"(a))
#define LDSM_X4_T(r, a)                                                        \
    asm volatile("ldmatrix.sync.aligned.m8n8.x4.trans.shared.b16 {%0,%1,%2,%3}, [%4];" \
        : "=r"((r)[0]), "=r"((r)[1]), "=r"((r)[2]), "=r"((r)[3]) : "r"(a))
#define MMA_BF16(d, A, B)                                                      \
    asm volatile("mma.sync.aligned.m16n8k16.row.col.f32.bf16.bf16.f32 "        \
        "{%0,%1,%2,%3}, {%4,%5,%6,%7}, {%8,%9}, {%0,%1,%2,%3};"                \
        : "+f"((d)[0]), "+f"((d)[1]), "+f"((d)[2]), "+f"((d)[3])               \
        : "r"((A)[0]), "r"((A)[1]), "r"((A)[2]), "r"((A)[3]),                  \
          "r"((B)[0]), "r"((B)[1]))
#define CPA(dst, src, sz) \
    asm volatile("cp.async.ca.shared.global [%0], [%1], 16, %2;" :: "r"(dst), "l"(src), "r"(sz))
#define CP_COMMIT asm volatile("cp.async.commit_group;" ::: "memory")
#define CP_WAIT0  asm volatile("cp.async.wait_group 0;" ::: "memory")

// ---------------- weight prep ----------------
__global__ void pack_qkv(const float* __restrict__ qp, const float* __restrict__ kp,
                         const float* __restrict__ wv,
                         __nv_bfloat16* __restrict__ hi, __nv_bfloat16* __restrict__ lo) {
    int idx = blockIdx.x * blockDim.x + threadIdx.x;
    if (idx >= 1024 * 512) return;
    int n = idx >> 9, d = idx & 511;
    float v;
    if (n < 256) {
        v = qp[((n >> 5) * 512 + d) * 32 + (n & 31)];
    } else if (n < 512) {
        int nn = n - 256;
        v = kp[((nn >> 5) * 512 + d) * 32 + (nn & 31)];
    } else {
        v = wv[(size_t)(n - 512) * 512 + d];
    }
    hilo(v, hi[idx], lo[idx]);
}

__global__ void conv_hilo(const float* __restrict__ in, __nv_bfloat16* __restrict__ hi,
                          __nv_bfloat16* __restrict__ lo, int n) {
    int i = blockIdx.x * blockDim.x + threadIdx.x;
    if (i >= n) return;
    hilo(in[i], hi[i], lo[i]);
}

// ---------------- HMMA bf16x3 GEMM with cp.async double buffering ----------------
// D[m][n] = sum_k A[m][k]*B[n][k], K=512, CTA tile 128x128, 8 warps.
// EPI: 0 none, 1 res+acc, 2 res+silu(acc), 3 tanh(acc/(softplus(extra[n])+1e-4))
// OMODE: 0 none, 1 full hilo out, 2 V-part hilo out (QKV: n>=512 -> Vh/Vl)
#define PAD 72
#define ARR (128 * PAD)
#define STAGEB (4 * ARR * 2)
#define GEMM_SMEM (2 * STAGEB)
template <int EPI, int OMODE>
__global__ void __launch_bounds__(256, 1) mma_gemm(
    const __nv_bfloat16* __restrict__ Ah, const __nv_bfloat16* __restrict__ Al,
    const __nv_bfloat16* __restrict__ Bh, const __nv_bfloat16* __restrict__ Bl,
    const float* __restrict__ Res, float* __restrict__ C,
    int Ntot, int NtotB, const float* __restrict__ extra,
    __nv_bfloat16* __restrict__ Oh, __nv_bfloat16* __restrict__ Ol)
{
    extern __shared__ __nv_bfloat16 smb[];
    uint32_t sbase = smem_u32(smb);

    int tid = threadIdx.x, lane = tid & 31, wid = tid >> 5;
    int warp_m = wid & 1, warp_n = wid >> 1;
    int m0 = blockIdx.y * 128, n0 = blockIdx.x * 128;

    uint32_t a_row = warp_m * 64 + (lane & 15);
    uint32_t a_ko  = (lane >> 4) * 8;
    uint32_t b_row = warp_n * 32 + (lane & 7);
    uint32_t b_ko  = ((lane >> 3) & 1) * 8;

    float acc[4][4][4] = {};

    // issue chunk 0 loads
    auto issue = [&](int c) {
        uint32_t st = (uint32_t)(c & 1) * STAGEB;
        int k0c = c * 64;
#pragma unroll
        for (int t = 0; t < 4; t++) {
            int idx = tid + t * 256;
            int r = idx >> 3, q = idx & 7;
            uint32_t so = st + (uint32_t)(r * PAD + q * 8) * 2;
            size_t g = (size_t)(m0 + r) * 512 + k0c + q * 8;
            CPA(sbase + so,            Ah + g, 16);
            CPA(sbase + so + ARR * 2,  Al + g, 16);
        }
#pragma unroll
        for (int t = 0; t < 4; t++) {
            int idx = tid + t * 256;
            int r = idx >> 3, q = idx & 7;
            uint32_t so = st + (uint32_t)(2 * ARR + r * PAD + q * 8) * 2;
            int n = n0 + r;
            int ok = (n < NtotB) ? 16 : 0;
            size_t g = (size_t)(ok ? n : 0) * 512 + k0c + q * 8;
            CPA(sbase + so,            Bh + g, ok);
            CPA(sbase + so + ARR * 2,  Bl + g, ok);
        }
        CP_COMMIT;
    };

    issue(0);
    for (int c = 0; c < 8; c++) {
        CP_WAIT0;
        __syncthreads();
        if (c < 7) issue(c + 1);

        uint32_t st = (uint32_t)(c & 1) * STAGEB;
        uint32_t uAh = sbase + st;
        uint32_t uAl = uAh + ARR * 2;
        uint32_t uBh = uAl + ARR * 2;
        uint32_t uBl = uBh + ARR * 2;

#pragma unroll
        for (int kk = 0; kk < 4; kk++) {
            uint32_t bh[4][2], bl[4][2];
#pragma unroll
            for (int ni = 0; ni < 4; ni++) {
                uint32_t off = ((b_row + ni * 8) * PAD + kk * 16 + b_ko) * 2;
                asm volatile("ldmatrix.sync.aligned.m8n8.x2.shared.b16 {%0,%1}, [%2];"
                    : "=r"(bh[ni][0]), "=r"(bh[ni][1]) : "r"(uBh + off));
                asm volatile("ldmatrix.sync.aligned.m8n8.x2.shared.b16 {%0,%1}, [%2];"
                    : "=r"(bl[ni][0]), "=r"(bl[ni][1]) : "r"(uBl + off));
            }
#pragma unroll
            for (int mi = 0; mi < 4; mi++) {
                uint32_t ah[4], al[4];
                uint32_t off = ((a_row + mi * 16) * PAD + kk * 16 + a_ko) * 2;
                LDSM_X4(ah, uAh + off);
                LDSM_X4(al, uAl + off);
#pragma unroll
                for (int ni = 0; ni < 4; ni++) {
                    MMA_BF16(acc[mi][ni], ah, bh[ni]);
                    MMA_BF16(acc[mi][ni], ah, bl[ni]);
                    MMA_BF16(acc[mi][ni], al, bh[ni]);
                }
            }
        }
        __syncthreads();
    }

    // epilogue
    int gid = lane >> 2, tig = lane & 3;
#pragma unroll
    for (int mi = 0; mi < 4; mi++) {
#pragma unroll
        for (int ni = 0; ni < 4; ni++) {
#pragma unroll
            for (int half = 0; half < 2; half++) {
                int m = m0 + warp_m * 64 + mi * 16 + gid + half * 8;
                int nbase = n0 + warp_n * 32 + ni * 8 + tig * 2;
#pragma unroll
                for (int e = 0; e < 2; e++) {
                    int n = nbase + e;
                    if (n >= Ntot) continue;
                    float v = acc[mi][ni][half * 2 + e];
                    if (EPI == 1) {
                        v += Res[(size_t)m * Ntot + n];
                    } else if (EPI == 2) {
                        float sg = 1.0f / (1.0f + __expf(-v));
                        v = Res[(size_t)m * Ntot + n] + v * sg;
                    } else if (EPI == 3) {
                        float ct = extra[n];
                        float sp = (ct > 20.0f) ? ct : log1pf(__expf(ct));
                        v = tanhf(v / (sp + 1e-4f));
                    }
                    if (OMODE == 2) {
                        if (n < 512) {
                            C[(size_t)m * Ntot + n] = v;
                        } else {
                            __nv_bfloat16 hx, lx;
                            hilo(v, hx, lx);
                            Oh[(size_t)m * 512 + (n - 512)] = hx;
                            Ol[(size_t)m * 512 + (n - 512)] = lx;
                        }
                    } else {
                        C[(size_t)m * Ntot + n] = v;
                        if (OMODE == 1) {
                            __nv_bfloat16 hx, lx;
                            hilo(v, hx, lx);
                            Oh[(size_t)m * 512 + n] = hx;
                            Ol[(size_t)m * 512 + n] = lx;
                        }
                    }
                }
            }
        }
    }
}

// ---------------- RoPE: fp32 qkv q/k cols -> bf16 hi/lo Q,K (+gain/scale fold) ----------------
__global__ void rope_kernel(const float* __restrict__ qkv, const float* __restrict__ q_gain,
                            __nv_bfloat16* __restrict__ Qh, __nv_bfloat16* __restrict__ Ql,
                            __nv_bfloat16* __restrict__ Kh, __nv_bfloat16* __restrict__ Kl) {
    int idx = blockIdx.x * blockDim.x + threadIdx.x;
    if (idx >= 2 * 4096 * 8 * 16) return;
    int i = idx & 15;
    int h = (idx >> 4) & 7;
    int m = (idx >> 7) & 4095;
    int which = idx >> 19;          // 0 = q, 1 = k
    int t = m & (T_LEN - 1);

    double fd = pow(10000.0, -(double)(2 * i) / 32.0);
    float ff = (float)fd;
    float ang = (float)t * ff;
    double ad = (double)ang;
    float c = (float)cos(ad);
    float s = (float)sin(ad);

    int col = which * 256 + h * 32;
    float x1 = qkv[(size_t)m * 1024 + col + i];
    float x2 = qkv[(size_t)m * 1024 + col + 16 + i];
    float o1 = x1 * c - x2 * s;
    float o2 = x2 * c + x1 * s;
    float scale = (which == 0) ? (q_gain[h] * 0.17677669529663687f) : 1.0f;
    o1 *= scale; o2 *= scale;

    __nv_bfloat16* dh = which ? Kh : Qh;
    __nv_bfloat16* dl = which ? Kl : Ql;
    size_t o = (size_t)m * 256 + h * 32 + i;
    __nv_bfloat16 h1, l1, h2, l2;
    hilo(o1, h1, l1); hilo(o2, h2, l2);
    dh[o] = h1; dl[o] = l1;
    dh[o + 16] = h2; dl[o + 16] = l2;
}

// ---------------- HMMA flash attention + self-align, bf16x3 ----------------
// BQ=128 (8 warps, 1 m16 each), K tiles of 64. grid (16, 8, 2), 256 thr.
#define ATTN_SMEM 49152
__global__ void __launch_bounds__(256, 2) attn_mma(
    const __nv_bfloat16* __restrict__ Qh_, const __nv_bfloat16* __restrict__ Ql_,
    const __nv_bfloat16* __restrict__ Kh_, const __nv_bfloat16* __restrict__ Kl_,
    const __nv_bfloat16* __restrict__ Vh_, const __nv_bfloat16* __restrict__ Vl_,
    __nv_bfloat16* __restrict__ yh, __nv_bfloat16* __restrict__ yl)
{
    extern __shared__ __nv_bfloat16 sb[];
    __nv_bfloat16* sQh = sb;             // [128][40]
    __nv_bfloat16* sQl = sQh + 128 * 40;
    __nv_bfloat16* sKh = sQl + 128 * 40; // [64][40]
    __nv_bfloat16* sKl = sKh + 64 * 40;
    __nv_bfloat16* sVh = sKl + 64 * 40;  // [64][72]
    __nv_bfloat16* sVl = sVh + 64 * 72;

    int qb = (int)gridDim.x - 1 - (int)blockIdx.x;
    int h = blockIdx.y, b = blockIdx.z;
    int tid = threadIdx.x, lane = tid & 31, w = tid >> 5;
    int q0 = qb * 128;
    int rw = q0 + w * 16;
    const size_t hb = (size_t)b * T_LEN;

    // load Q tile (hi/lo)
    for (int i = tid; i < 512; i += 256) {
        int r = i >> 2, seg = i & 3;
        size_t g = (hb + q0 + r) * 256 + h * 32 + seg * 8;
        *(float4*)(sQh + r * 40 + seg * 8) = *(const float4*)(Qh_ + g);
        *(float4*)(sQl + r * 40 + seg * 8) = *(const float4*)(Ql_ + g);
    }
    __syncthreads();

    // Q fragments (regs, reused all tiles)
    uint32_t qfh[2][4], qfl[2][4];
    {
        int mrow = (lane & 7) + 8 * ((lane >> 3) & 1);
        int koff = 8 * (lane >> 4);
#pragma unroll
        for (int kj = 0; kj < 2; kj++) {
            LDSM_X4(qfh[kj], smem_u32(sQh + (w * 16 + mrow) * 40 + kj * 16 + koff));
            LDSM_X4(qfl[kj], smem_u32(sQl + (w * 16 + mrow) * 40 + kj * 16 + koff));
        }
    }

    float m_[2] = {-1e30f, -1e30f}, l_[2] = {0.f, 0.f};
    float o[8][4] = {};

    int ntiles = 2 * qb + 2;
    for (int j = 0; j < ntiles; j++) {
        int k0 = j * 64;
        __syncthreads();
        // load K (64x32) and V (64x64) hi/lo
        {
            int r = tid >> 2, seg = tid & 3;
            size_t g = (hb + k0 + r) * 256 + h * 32 + seg * 8;
            *(float4*)(sKh + r * 40 + seg * 8) = *(const float4*)(Kh_ + g);
            *(float4*)(sKl + r * 40 + seg * 8) = *(const float4*)(Kl_ + g);
        }
        for (int i = tid; i < 512; i += 256) {
            int r = i >> 3, seg = i & 7;
            size_t g = (hb + k0 + r) * 512 + h * 64 + seg * 8;
            *(float4*)(sVh + r * 72 + seg * 8) = *(const float4*)(Vh_ + g);
            *(float4*)(sVl + r * 72 + seg * 8) = *(const float4*)(Vl_ + g);
        }
        __syncthreads();

        // S = Q K^T
        float s[8][4] = {};
        {
            int nrow = (lane & 7) + 8 * (lane >> 4);
            int koff = 8 * ((lane >> 3) & 1);
#pragma unroll
            for (int kj = 0; kj < 2; kj++) {
#pragma unroll
                for (int p = 0; p < 4; p++) {
                    uint32_t kb_h[4], kb_l[4];
                    LDSM_X4(kb_h, smem_u32(sKh + (p * 16 + nrow) * 40 + kj * 16 + koff));
                    LDSM_X4(kb_l, smem_u32(sKl + (p * 16 + nrow) * 40 + kj * 16 + koff));
                    MMA_BF16(s[2 * p],     qfh[kj], kb_h);
                    MMA_BF16(s[2 * p],     qfh[kj], kb_l);
                    MMA_BF16(s[2 * p],     qfl[kj], kb_h);
                    MMA_BF16(s[2 * p + 1], qfh[kj], kb_h + 2);
                    MMA_BF16(s[2 * p + 1], qfh[kj], kb_l + 2);
                    MMA_BF16(s[2 * p + 1], qfl[kj], kb_h + 2);
                }
            }
        }

        // causal mask
        if (k0 + 63 > rw) {
#pragma unroll
            for (int nt = 0; nt < 8; nt++)
#pragma unroll
                for (int e = 0; e < 4; e++) {
                    int col = k0 + nt * 8 + (lane & 3) * 2 + (e & 1);
                    int row = rw + (lane >> 2) + (e >> 1) * 8;
                    if (col > row) s[nt][e] = -1e30f;
                }
        }

        // online softmax (quad reductions)
        float alpha[2];
#pragma unroll
        for (int half = 0; half < 2; half++) {
            float mx = -1e30f;
#pragma unroll
            for (int nt = 0; nt < 8; nt++)
                mx = fmaxf(mx, fmaxf(s[nt][2 * half], s[nt][2 * half + 1]));
            mx = fmaxf(mx, __shfl_xor_sync(0xffffffffu, mx, 1));
            mx = fmaxf(mx, __shfl_xor_sync(0xffffffffu, mx, 2));
            float mnew = fmaxf(m_[half], mx);
            alpha[half] = __expf(m_[half] - mnew);
            m_[half] = mnew;
            float sum = 0.f;
#pragma unroll
            for (int nt = 0; nt < 8; nt++) {
                s[nt][2 * half]     = __expf(s[nt][2 * half] - mnew);
                s[nt][2 * half + 1] = __expf(s[nt][2 * half + 1] - mnew);
                sum += s[nt][2 * half] + s[nt][2 * half + 1];
            }
            sum += __shfl_xor_sync(0xffffffffu, sum, 1);
            sum += __shfl_xor_sync(0xffffffffu, sum, 2);
            l_[half] = l_[half] * alpha[half] + sum;
        }
#pragma unroll
        for (int dt = 0; dt < 8; dt++) {
            o[dt][0] *= alpha[0]; o[dt][1] *= alpha[0];
            o[dt][2] *= alpha[1]; o[dt][3] *= alpha[1];
        }

        // pack P fragments (C-frag -> A-frag identity)
        uint32_t pah[4][4], pal[4][4];
#pragma unroll
        for (int kj = 0; kj < 4; kj++) {
            packhl(s[2 * kj][0],     s[2 * kj][1],     pah[kj][0], pal[kj][0]);
            packhl(s[2 * kj][2],     s[2 * kj][3],     pah[kj][1], pal[kj][1]);
            packhl(s[2 * kj + 1][0], s[2 * kj + 1][1], pah[kj][2], pal[kj][2]);
            packhl(s[2 * kj + 1][2], s[2 * kj + 1][3], pah[kj][3], pal[kj][3]);
        }

        // O += P V  (V via ldmatrix.trans)
        {
            int vrow = lane & 15;
            int vcol = 8 * (lane >> 4);
#pragma unroll
            for (int kj = 0; kj < 4; kj++) {
#pragma unroll
                for (int p = 0; p < 4; p++) {
                    uint32_t vb_h[4], vb_l[4];
                    LDSM_X4_T(vb_h, smem_u32(sVh + (kj * 16 + vrow) * 72 + p * 16 + vcol));
                    LDSM_X4_T(vb_l, smem_u32(sVl + (kj * 16 + vrow) * 72 + p * 16 + vcol));
                    MMA_BF16(o[2 * p],     pah[kj], vb_h);
                    MMA_BF16(o[2 * p],     pah[kj], vb_l);
                    MMA_BF16(o[2 * p],     pal[kj], vb_h);
                    MMA_BF16(o[2 * p + 1], pah[kj], vb_h + 2);
                    MMA_BF16(o[2 * p + 1], pah[kj], vb_l + 2);
                    MMA_BF16(o[2 * p + 1], pal[kj], vb_h + 2);
                }
            }
        }
    }

    // epilogue: self-align removal + 1/l + hilo write
#pragma unroll
    for (int half = 0; half < 2; half++) {
        int row = rw + (lane >> 2) + half * 8;
        float dp = 0.f, nn = 0.f;
        float vv[8][2];
#pragma unroll
        for (int dt = 0; dt < 8; dt++) {
            int c0 = dt * 8 + (lane & 3) * 2;
            size_t g = (hb + row) * 512 + h * 64 + c0;
            __nv_bfloat162 th = *(const __nv_bfloat162*)(Vh_ + g);
            __nv_bfloat162 tl = *(const __nv_bfloat162*)(Vl_ + g);
            float v0 = __bfloat162float(th.x) + __bfloat162float(tl.x);
            float v1 = __bfloat162float(th.y) + __bfloat162float(tl.y);
            vv[dt][0] = v0; vv[dt][1] = v1;
            dp += o[dt][2 * half] * v0 + o[dt][2 * half + 1] * v1;
            nn += v0 * v0 + v1 * v1;
        }
        dp += __shfl_xor_sync(0xffffffffu, dp, 1);
        dp += __shfl_xor_sync(0xffffffffu, dp, 2);
        nn += __shfl_xor_sync(0xffffffffu, nn, 1);
        nn += __shfl_xor_sync(0xffffffffu, nn, 2);
        float coef = dp / fmaxf(nn, 1e-24f);
        float linv = 1.0f / l_[half];
#pragma unroll
        for (int dt = 0; dt < 8; dt++) {
            int c0 = dt * 8 + (lane & 3) * 2;
            size_t g = (hb + row) * 512 + h * 64 + c0;
            float y0 = (o[dt][2 * half]     - coef * vv[dt][0]) * linv;
            float y1 = (o[dt][2 * half + 1] - coef * vv[dt][1]) * linv;
            uint32_t ph, pl;
            packhl(y0, y1, ph, pl);
            *(uint32_t*)(yh + g) = ph;
            *(uint32_t*)(yl + g) = pl;
        }
    }
}

// ---------------- layernorm -> bf16 hi/lo ----------------
__global__ void ln_hilo(const float* __restrict__ in, const float* __restrict__ g,
                        const float* __restrict__ bta,
                        __nv_bfloat16* __restrict__ oh, __nv_bfloat16* __restrict__ ol) {
    int row = blockIdx.x * 8 + (threadIdx.x >> 5);
    int lane = threadIdx.x & 31;
    const float* p = in + (size_t)row * 512;
    float v[16];
    float s = 0.f;
#pragma unroll
    for (int j = 0; j < 16; j++) { v[j] = p[lane + 32 * j]; s += v[j]; }
#pragma unroll
    for (int off = 16; off; off >>= 1) s += __shfl_xor_sync(0xffffffffu, s, off);
    float mean = s * (1.0f / 512.0f);
    float s2 = 0.f;
#pragma unroll
    for (int j = 0; j < 16; j++) { float d = v[j] - mean; s2 += d * d; }
#pragma unroll
    for (int off = 16; off; off >>= 1) s2 += __shfl_xor_sync(0xffffffffu, s2, off);
    float r = rsqrtf(s2 * (1.0f / 512.0f) + 1e-5f);
#pragma unroll
    for (int j = 0; j < 16; j++) {
        int c = lane + 32 * j;
        float ov = (v[j] - mean) * r * g[c] + bta[c];
        __nv_bfloat16 hx, lx;
        hilo(ov, hx, lx);
        oh[(size_t)row * 512 + c] = hx;
        ol[(size_t)row * 512 + c] = lx;
    }
}

// ---------------- RMS norm -> bf16 hi/lo ----------------
__global__ void rms_hilo(const float* __restrict__ in,
                         __nv_bfloat16* __restrict__ oh, __nv_bfloat16* __restrict__ ol) {
    int row = blockIdx.x * 8 + (threadIdx.x >> 5);
    int lane = threadIdx.x & 31;
    const float* p = in + (size_t)row * 512;
    float v[16];
    float s2 = 0.f;
#pragma unroll
    for (int j = 0; j < 16; j++) { v[j] = p[lane + 32 * j]; s2 += v[j] * v[j]; }
#pragma unroll
    for (int off = 16; off; off >>= 1) s2 += __shfl_xor_sync(0xffffffffu, s2, off);
    float r = rsqrtf(s2 * (1.0f / 512.0f) + 1e-6f);
#pragma unroll
    for (int j = 0; j < 16; j++) {
        float ov = v[j] * r;
        __nv_bfloat16 hx, lx;
        hilo(ov, hx, lx);
        oh[(size_t)row * 512 + lane + 32 * j] = hx;
        ol[(size_t)row * 512 + lane + 32 * j] = lx;
    }
}

// ---------------- launch ----------------
extern "C" void kernel_launch(void* const* d_in, const int* in_sizes, int n_in,
                              void* d_out, int out_size) {
    const float* x      = (const float*)d_in[0];
    const float* qp     = (const float*)d_in[1];
    const float* kp     = (const float*)d_in[2];
    const float* wv     = (const float*)d_in[3];
    const float* wproj  = (const float*)d_in[4];
    const float* qg     = (const float*)d_in[5];
    const float* ew0    = (const float*)d_in[6];
    const float* g1     = (const float*)d_in[7];
    const float* b1     = (const float*)d_in[8];
    const float* ew1    = (const float*)d_in[9];
    const float* g2     = (const float*)d_in[10];
    const float* b2     = (const float*)d_in[11];
    const float* ew2    = (const float*)d_in[12];
    const float* ewout  = (const float*)d_in[13];
    const float* ctemp  = (const float*)d_in[14];
    float* out = (float*)d_out;

    float *qkv, *hb, *t1, *t2, *t3;
    __nv_bfloat16 *A0h, *A0l, *A1h, *A1l, *Wh, *Wl, *Qh, *Ql, *Kh, *Kl, *Vh, *Vl;
    cudaGetSymbolAddress((void**)&qkv, g_qkv);
    cudaGetSymbolAddress((void**)&hb,  g_h);
    cudaGetSymbolAddress((void**)&t1,  g_t1);
    cudaGetSymbolAddress((void**)&t2,  g_t2);
    cudaGetSymbolAddress((void**)&t3,  g_t3);
    cudaGetSymbolAddress((void**)&A0h, g_A0h);
    cudaGetSymbolAddress((void**)&A0l, g_A0l);
    cudaGetSymbolAddress((void**)&A1h, g_A1h);
    cudaGetSymbolAddress((void**)&A1l, g_A1l);
    cudaGetSymbolAddress((void**)&Wh,  g_Wh);
    cudaGetSymbolAddress((void**)&Wl,  g_Wl);
    cudaGetSymbolAddress((void**)&Qh,  g_Qh);
    cudaGetSymbolAddress((void**)&Ql,  g_Ql);
    cudaGetSymbolAddress((void**)&Kh,  g_Kh);
    cudaGetSymbolAddress((void**)&Kl,  g_Kl);
    cudaGetSymbolAddress((void**)&Vh,  g_Vh);
    cudaGetSymbolAddress((void**)&Vl,  g_Vl);

    cudaFuncSetAttribute(attn_mma, cudaFuncAttributeMaxDynamicSharedMemorySize, ATTN_SMEM);
    cudaFuncSetAttribute(mma_gemm<0, 0>, cudaFuncAttributeMaxDynamicSharedMemorySize, GEMM_SMEM);
    cudaFuncSetAttribute(mma_gemm<0, 2>, cudaFuncAttributeMaxDynamicSharedMemorySize, GEMM_SMEM);
    cudaFuncSetAttribute(mma_gemm<1, 1>, cudaFuncAttributeMaxDynamicSharedMemorySize, GEMM_SMEM);
    cudaFuncSetAttribute(mma_gemm<2, 0>, cudaFuncAttributeMaxDynamicSharedMemorySize, GEMM_SMEM);
    cudaFuncSetAttribute(mma_gemm<3, 0>, cudaFuncAttributeMaxDynamicSharedMemorySize, GEMM_SMEM);

    // weight prep
    pack_qkv<<<2048, 256>>>(qp, kp, wv, Wh, Wl);
    conv_hilo<<<1024, 256>>>(wproj, Wh + 1024 * 512, Wl + 1024 * 512, 512 * 512);
    conv_hilo<<<1024, 256>>>(ew0,   Wh + 1536 * 512, Wl + 1536 * 512, 512 * 512);
    conv_hilo<<<1024, 256>>>(ew1,   Wh + 2048 * 512, Wl + 2048 * 512, 512 * 512);
    conv_hilo<<<1024, 256>>>(ew2,   Wh + 2560 * 512, Wl + 2560 * 512, 512 * 512);
    conv_hilo<<<64,   256>>>(ewout, Wh + 3072 * 512, Wl + 3072 * 512, 32 * 512);
    conv_hilo<<<8192, 256>>>(x, A0h, A0l, 4096 * 512);

    // 1. QKV (q,k fp32 -> qkv; v -> Vh/Vl hilo)
    mma_gemm<0, 2><<<dim3(8, 32), 256, GEMM_SMEM>>>(A0h, A0l, Wh, Wl, nullptr, qkv,
                                                    1024, 1024, nullptr, Vh, Vl);
    // 2. RoPE -> Q/K hilo
    rope_kernel<<<4096, 256>>>(qkv, qg, Qh, Ql, Kh, Kl);
    // 3. HMMA flash attention -> A1 hilo
    attn_mma<<<dim3(16, 8, 2), 256, ATTN_SMEM>>>(Qh, Ql, Kh, Kl, Vh, Vl, A1h, A1l);
    // 4. h = x + y @ wproj^T  (+ hilo(h) -> A0)
    mma_gemm<1, 1><<<dim3(4, 32), 256, GEMM_SMEM>>>(A1h, A1l, Wh + 1024 * 512, Wl + 1024 * 512,
                                                    x, hb, 512, 512, nullptr, A0h, A0l);
    // 5. t1 = h @ ew0^T
    mma_gemm<0, 0><<<dim3(4, 32), 256, GEMM_SMEM>>>(A0h, A0l, Wh + 1536 * 512, Wl + 1536 * 512,
                                                    nullptr, t1, 512, 512, nullptr, nullptr, nullptr);
    ln_hilo<<<512, 256>>>(t1, g1, b1, A1h, A1l);
    // 6. t3 = h + silu(ln1 @ ew1^T)
    mma_gemm<2, 0><<<dim3(4, 32), 256, GEMM_SMEM>>>(A1h, A1l, Wh + 2048 * 512, Wl + 2048 * 512,
                                                    hb, t3, 512, 512, nullptr, nullptr, nullptr);
    ln_hilo<<<512, 256>>>(t3, g2, b2, A0h, A0l);
    // 7. t2 = t3 + silu(ln2 @ ew2^T)
    mma_gemm<2, 0><<<dim3(4, 32), 256, GEMM_SMEM>>>(A0h, A0l, Wh + 2560 * 512, Wl + 2560 * 512,
                                                    t3, t2, 512, 512, nullptr, nullptr, nullptr);
    // 8. rms + head
    rms_hilo<<<512, 256>>>(t2, A1h, A1l);
    mma_gemm<3, 0><<<dim3(1, 32), 256, GEMM_SMEM>>>(A1h, A1l, Wh + 3072 * 512, Wl + 3072 * 512,
                                                    nullptr, out, 32, 32, ctemp, nullptr, nullptr);
}

// round 10
// speedup vs baseline: 3.2763x; 1.5662x over previous
#include <cuda_runtime.h>
#include <cuda_bf16.h>
#include <math.h>
#include <math_constants.h>
#include <cstdint>

#define T_LEN 2048

// ---------------- scratch (no allocations allowed) ----------------
__device__ float g_h [4096 * 512];
__device__ float g_t1[4096 * 512];
__device__ float g_t2[4096 * 512];
__device__ float g_t3[4096 * 512];
__device__ float g_rope[2048 * 16 * 2];
__device__ __nv_bfloat16 g_A0h[4096 * 512], g_A0l[4096 * 512];
__device__ __nv_bfloat16 g_A1h[4096 * 512], g_A1l[4096 * 512];
__device__ __nv_bfloat16 g_Qh[4096 * 256], g_Ql[4096 * 256];
__device__ __nv_bfloat16 g_Kh[4096 * 256], g_Kl[4096 * 256];
__device__ __nv_bfloat16 g_Vh[4096 * 512], g_Vl[4096 * 512];
// weight rows: [0:1024) qkv | [1024:1536) wproj | [1536:2048) ew0 | [2048:2560) ew1 | [2560:3072) ew2 | [3072:3104) ewout
__device__ __nv_bfloat16 g_Wh[3104 * 512], g_Wl[3104 * 512];

// ---------------- helpers ----------------
static __device__ __forceinline__ uint32_t smem_u32(const void* p) {
    uint32_t a;
    asm("{ .reg .u64 t; cvta.to.shared.u64 t, %1; cvt.u32.u64 %0, t; }" : "=r"(a) : "l"(p));
    return a;
}
static __device__ __forceinline__ void hilo(float v, __nv_bfloat16& h, __nv_bfloat16& l) {
    h = __float2bfloat16(v);
    l = __float2bfloat16(v - __bfloat162float(h));
}
static __device__ __forceinline__ void packhl(float a, float b, uint32_t& ph, uint32_t& pl) {
    __nv_bfloat162 hp, lp;
    hp.x = __float2bfloat16(a);
    hp.y = __float2bfloat16(b);
    lp.x = __float2bfloat16(a - __bfloat162float(hp.x));
    lp.y = __float2bfloat16(b - __bfloat162float(hp.y));
    ph = *(uint32_t*)&hp;
    pl = *(uint32_t*)&lp;
}

#define LDSM_X4(r, a)                                                          \
    asm volatile("ldmatrix.sync.aligned.m8n8.x4.shared.b16 {%0,%1,%2,%3}, [%4];" \
        : "=r"((r)[0]), "=r"((r)[1]), "=r"((r)[2]), "=r"((r)[3]) : "r"(a))
#define LDSM_X4_T(r, a)                                                        \
    asm volatile("ldmatrix.sync.aligned.m8n8.x4.trans.shared.b16 {%0,%1,%2,%3}, [%4];" \
        : "=r"((r)[0]), "=r"((r)[1]), "=r"((r)[2]), "=r"((r)[3]) : "r"(a))
#define MMA_BF16(d, A, B)                                                      \
    asm volatile("mma.sync.aligned.m16n8k16.row.col.f32.bf16.bf16.f32 "        \
        "{%0,%1,%2,%3}, {%4,%5,%6,%7}, {%8,%9}, {%0,%1,%2,%3};"                \
        : "+f"((d)[0]), "+f"((d)[1]), "+f"((d)[2]), "+f"((d)[3])               \
        : "r"((A)[0]), "r"((A)[1]), "r"((A)[2]), "r"((A)[3]),                  \
          "r"((B)[0]), "r"((B)[1]))
#define CPA(dst, src, sz) \
    asm volatile("cp.async.ca.shared.global [%0], [%1], 16, %2;" :: "r"(dst), "l"(src), "r"(sz))
#define CP_COMMIT asm volatile("cp.async.commit_group;" ::: "memory")
#define CP_WAIT0  asm volatile("cp.async.wait_group 0;" ::: "memory")
#define CP_WAIT1  asm volatile("cp.async.wait_group 1;" ::: "memory")

// ---------------- fused prep: weights hilo + x hilo + rope table ----------------
__global__ void prep_kernel(
    const float* __restrict__ x, const float* __restrict__ qp, const float* __restrict__ kp,
    const float* __restrict__ wv, const float* __restrict__ wproj,
    const float* __restrict__ ew0, const float* __restrict__ ew1,
    const float* __restrict__ ew2, const float* __restrict__ ewout,
    __nv_bfloat16* __restrict__ Wh, __nv_bfloat16* __restrict__ Wl,
    __nv_bfloat16* __restrict__ A0h, __nv_bfloat16* __restrict__ A0l,
    float* __restrict__ rope)
{
    int idx = blockIdx.x * blockDim.x + threadIdx.x;
    if (idx < 524288) {
        // qkv weight pack: n = [q(256)|k(256)|v(512)], Wpack[n][d]
        int n = idx >> 9, d = idx & 511;
        float v;
        if (n < 256) v = qp[((n >> 5) * 512 + d) * 32 + (n & 31)];
        else if (n < 512) { int nn = n - 256; v = kp[((nn >> 5) * 512 + d) * 32 + (nn & 31)]; }
        else v = wv[(size_t)(n - 512) * 512 + d];
        hilo(v, Wh[idx], Wl[idx]);
    } else if (idx < 786432) {
        int i = idx - 524288;
        hilo(wproj[i], Wh[1024 * 512 + i], Wl[1024 * 512 + i]);
    } else if (idx < 1048576) {
        int i = idx - 786432;
        hilo(ew0[i], Wh[1536 * 512 + i], Wl[1536 * 512 + i]);
    } else if (idx < 1310720) {
        int i = idx - 1048576;
        hilo(ew1[i], Wh[2048 * 512 + i], Wl[2048 * 512 + i]);
    } else if (idx < 1572864) {
        int i = idx - 1310720;
        hilo(ew2[i], Wh[2560 * 512 + i], Wl[2560 * 512 + i]);
    } else if (idx < 1589248) {
        int i = idx - 1572864;
        hilo(ewout[i], Wh[3072 * 512 + i], Wl[3072 * 512 + i]);
    } else if (idx < 3686400) {
        int i = idx - 1589248;
        hilo(x[i], A0h[i], A0l[i]);
    } else if (idx < 3719168) {
        int i2 = idx - 3686400;       // t*16 + i
        int t = i2 >> 4, i = i2 & 15;
        double fd = pow(10000.0, -(double)(2 * i) / 32.0);
        float ang = (float)t * (float)fd;
        double ad = (double)ang;
        rope[i2 * 2]     = (float)cos(ad);
        rope[i2 * 2 + 1] = (float)sin(ad);
    }
}

// ---------------- HMMA bf16x3 GEMM with cp.async double buffering ----------------
// D[m][n] = sum_k A[m][k]*B[n][k], K=512, CTA tile 128x128, 8 warps.
// EPI: 0 none, 1 res+acc, 2 res+silu(acc), 3 tanh(acc/(softplus(extra[n])+1e-4))
// OMODE: 0 none, 1 full hilo out, 2 QKV fused epilogue (rope for n<512, V hilo for n>=512)
#define PAD 72
#define ARR (128 * PAD)
#define STAGEB (4 * ARR * 2)
#define GEMM_SMEM (2 * STAGEB)
template <int EPI, int OMODE>
__global__ void __launch_bounds__(256, 1) mma_gemm(
    const __nv_bfloat16* __restrict__ Ah, const __nv_bfloat16* __restrict__ Al,
    const __nv_bfloat16* __restrict__ Bh, const __nv_bfloat16* __restrict__ Bl,
    const float* __restrict__ Res, float* __restrict__ C,
    int Ntot, int NtotB, const float* __restrict__ extra,
    __nv_bfloat16* __restrict__ Oh, __nv_bfloat16* __restrict__ Ol,
    __nv_bfloat16* __restrict__ Qh, __nv_bfloat16* __restrict__ Ql,
    __nv_bfloat16* __restrict__ Kh, __nv_bfloat16* __restrict__ Kl,
    const float* __restrict__ rope_tab, const float* __restrict__ qgain)
{
    extern __shared__ __nv_bfloat16 smb[];
    uint32_t sbase = smem_u32(smb);

    int tid = threadIdx.x, lane = tid & 31, wid = tid >> 5;
    int warp_m = wid & 1, warp_n = wid >> 1;
    int m0 = blockIdx.y * 128, n0 = blockIdx.x * 128;

    uint32_t a_row = warp_m * 64 + (lane & 15);
    uint32_t a_ko  = (lane >> 4) * 8;
    uint32_t b_row = warp_n * 32 + (lane & 7);
    uint32_t b_ko  = ((lane >> 3) & 1) * 8;

    float acc[4][4][4] = {};

    auto issue = [&](int c) {
        uint32_t st = (uint32_t)(c & 1) * STAGEB;
        int k0c = c * 64;
#pragma unroll
        for (int t = 0; t < 4; t++) {
            int idx = tid + t * 256;
            int r = idx >> 3, q = idx & 7;
            uint32_t so = st + (uint32_t)(r * PAD + q * 8) * 2;
            size_t g = (size_t)(m0 + r) * 512 + k0c + q * 8;
            CPA(sbase + so,            Ah + g, 16);
            CPA(sbase + so + ARR * 2,  Al + g, 16);
        }
#pragma unroll
        for (int t = 0; t < 4; t++) {
            int idx = tid + t * 256;
            int r = idx >> 3, q = idx & 7;
            uint32_t so = st + (uint32_t)(2 * ARR + r * PAD + q * 8) * 2;
            int n = n0 + r;
            int ok = (n < NtotB) ? 16 : 0;
            size_t g = (size_t)(ok ? n : 0) * 512 + k0c + q * 8;
            CPA(sbase + so,            Bh + g, ok);
            CPA(sbase + so + ARR * 2,  Bl + g, ok);
        }
        CP_COMMIT;
    };

    issue(0);
    for (int c = 0; c < 8; c++) {
        CP_WAIT0;
        __syncthreads();
        if (c < 7) issue(c + 1);

        uint32_t st = (uint32_t)(c & 1) * STAGEB;
        uint32_t uAh = sbase + st;
        uint32_t uAl = uAh + ARR * 2;
        uint32_t uBh = uAl + ARR * 2;
        uint32_t uBl = uBh + ARR * 2;

#pragma unroll
        for (int kk = 0; kk < 4; kk++) {
            uint32_t bh[4][2], bl[4][2];
#pragma unroll
            for (int ni = 0; ni < 4; ni++) {
                uint32_t off = ((b_row + ni * 8) * PAD + kk * 16 + b_ko) * 2;
                asm volatile("ldmatrix.sync.aligned.m8n8.x2.shared.b16 {%0,%1}, [%2];"
                    : "=r"(bh[ni][0]), "=r"(bh[ni][1]) : "r"(uBh + off));
                asm volatile("ldmatrix.sync.aligned.m8n8.x2.shared.b16 {%0,%1}, [%2];"
                    : "=r"(bl[ni][0]), "=r"(bl[ni][1]) : "r"(uBl + off));
            }
#pragma unroll
            for (int mi = 0; mi < 4; mi++) {
                uint32_t ah[4], al[4];
                uint32_t off = ((a_row + mi * 16) * PAD + kk * 16 + a_ko) * 2;
                LDSM_X4(ah, uAh + off);
                LDSM_X4(al, uAl + off);
#pragma unroll
                for (int ni = 0; ni < 4; ni++) {
                    MMA_BF16(acc[mi][ni], ah, bh[ni]);
                    MMA_BF16(acc[mi][ni], ah, bl[ni]);
                    MMA_BF16(acc[mi][ni], al, bh[ni]);
                }
            }
        }
        __syncthreads();
    }

    // epilogue
    int gid = lane >> 2, tig = lane & 3;

    if (OMODE == 2) {
        int colbase = n0 + warp_n * 32;   // warp-uniform, one 32-col head group
        if (colbase < 512) {
            // q/k region: rope rotate in-register, pairs (ni, ni+2)
            int which = colbase >= 256;
            int hh = (colbase >> 5) & 7;
            float scale = which ? 1.0f : (qgain[hh] * 0.17677669529663687f);
            __nv_bfloat16* dh = which ? Kh : Qh;
            __nv_bfloat16* dl = which ? Kl : Ql;
            int off0 = colbase & 255;
#pragma unroll
            for (int mi = 0; mi < 4; mi++) {
#pragma unroll
                for (int half = 0; half < 2; half++) {
                    int m = m0 + warp_m * 64 + mi * 16 + gid + half * 8;
                    int t = m & (T_LEN - 1);
#pragma unroll
                    for (int ni = 0; ni < 2; ni++) {
#pragma unroll
                        for (int e = 0; e < 2; e++) {
                            int i = ni * 8 + tig * 2 + e;
                            float x1 = acc[mi][ni][half * 2 + e];
                            float x2 = acc[mi][ni + 2][half * 2 + e];
                            float cth = rope_tab[(t * 16 + i) * 2];
                            float sth = rope_tab[(t * 16 + i) * 2 + 1];
                            float o1 = (x1 * cth - x2 * sth) * scale;
                            float o2 = (x2 * cth + x1 * sth) * scale;
                            __nv_bfloat16 h1, l1, h2, l2;
                            hilo(o1, h1, l1); hilo(o2, h2, l2);
                            size_t base = (size_t)m * 256 + off0 + i;
                            dh[base] = h1;      dl[base] = l1;
                            dh[base + 16] = h2; dl[base + 16] = l2;
                        }
                    }
                }
            }
        } else {
            // V region: hilo split
#pragma unroll
            for (int mi = 0; mi < 4; mi++) {
#pragma unroll
                for (int ni = 0; ni < 4; ni++) {
#pragma unroll
                    for (int half = 0; half < 2; half++) {
                        int m = m0 + warp_m * 64 + mi * 16 + gid + half * 8;
                        int nb = colbase + ni * 8 + tig * 2;
#pragma unroll
                        for (int e = 0; e < 2; e++) {
                            int n = nb + e;
                            __nv_bfloat16 hx, lx;
                            hilo(acc[mi][ni][half * 2 + e], hx, lx);
                            Oh[(size_t)m * 512 + (n - 512)] = hx;
                            Ol[(size_t)m * 512 + (n - 512)] = lx;
                        }
                    }
                }
            }
        }
        return;
    }

#pragma unroll
    for (int mi = 0; mi < 4; mi++) {
#pragma unroll
        for (int ni = 0; ni < 4; ni++) {
#pragma unroll
            for (int half = 0; half < 2; half++) {
                int m = m0 + warp_m * 64 + mi * 16 + gid + half * 8;
                int nbase = n0 + warp_n * 32 + ni * 8 + tig * 2;
#pragma unroll
                for (int e = 0; e < 2; e++) {
                    int n = nbase + e;
                    if (n >= Ntot) continue;
                    float v = acc[mi][ni][half * 2 + e];
                    if (EPI == 1) {
                        v += Res[(size_t)m * Ntot + n];
                    } else if (EPI == 2) {
                        float sg = 1.0f / (1.0f + __expf(-v));
                        v = Res[(size_t)m * Ntot + n] + v * sg;
                    } else if (EPI == 3) {
                        float ct = extra[n];
                        float sp = (ct > 20.0f) ? ct : log1pf(__expf(ct));
                        v = tanhf(v / (sp + 1e-4f));
                    }
                    C[(size_t)m * Ntot + n] = v;
                    if (OMODE == 1) {
                        __nv_bfloat16 hx, lx;
                        hilo(v, hx, lx);
                        Oh[(size_t)m * 512 + n] = hx;
                        Ol[(size_t)m * 512 + n] = lx;
                    }
                }
            }
        }
    }
}

// ---------------- HMMA flash attention + self-align, bf16x3, cp.async double-buffered ----------------
// BQ=128 (8 warps), K tiles of 64, 2-stage K/V pipeline. grid (16, 8, 2), 256 thr.
#define AQ_E   (128 * 40)                 // one Q array (elems)
#define AK_E   (64 * 40)
#define AV_E   (64 * 72)
#define ASTAGE (2 * AK_E + 2 * AV_E)      // 14336 elems per stage
#define ATTN_SMEM ((2 * AQ_E + 2 * ASTAGE) * 2)   // 77824 bytes
__global__ void __launch_bounds__(256, 2) attn_mma(
    const __nv_bfloat16* __restrict__ Qh_, const __nv_bfloat16* __restrict__ Ql_,
    const __nv_bfloat16* __restrict__ Kh_, const __nv_bfloat16* __restrict__ Kl_,
    const __nv_bfloat16* __restrict__ Vh_, const __nv_bfloat16* __restrict__ Vl_,
    __nv_bfloat16* __restrict__ yh, __nv_bfloat16* __restrict__ yl)
{
    extern __shared__ __nv_bfloat16 sb[];
    __nv_bfloat16* sQh = sb;
    __nv_bfloat16* sQl = sQh + AQ_E;
    __nv_bfloat16* stage0 = sQl + AQ_E;

    int qb = (int)gridDim.x - 1 - (int)blockIdx.x;
    int h = blockIdx.y, b = blockIdx.z;
    int tid = threadIdx.x, lane = tid & 31, w = tid >> 5;
    int q0 = qb * 128;
    int rw = q0 + w * 16;
    const size_t hb = (size_t)b * T_LEN;
    int ntiles = 2 * qb + 2;

    auto issueKV = [&](int j) {
        int k0 = j * 64;
        uint32_t st = smem_u32(stage0 + (j & 1) * ASTAGE);
        {   // K: 64 rows x 4 segs of 8, exactly 256 threads
            int r = tid >> 2, seg = tid & 3;
            size_t g = (hb + k0 + r) * 256 + h * 32 + seg * 8;
            uint32_t d = st + (uint32_t)(r * 40 + seg * 8) * 2;
            CPA(d,              Kh_ + g, 16);
            CPA(d + AK_E * 2,   Kl_ + g, 16);
        }
#pragma unroll
        for (int t2 = 0; t2 < 2; t2++) {   // V: 64 rows x 8 segs
            int idx = tid + t2 * 256;
            int r = idx >> 3, seg = idx & 7;
            size_t g = (hb + k0 + r) * 512 + h * 64 + seg * 8;
            uint32_t d = st + (uint32_t)(2 * AK_E + r * 72 + seg * 8) * 2;
            CPA(d,              Vh_ + g, 16);
            CPA(d + AV_E * 2,   Vl_ + g, 16);
        }
        CP_COMMIT;
    };

    issueKV(0);

    // load Q tile (hi/lo) with plain loads
    for (int i = tid; i < 512; i += 256) {
        int r = i >> 2, seg = i & 3;
        size_t g = (hb + q0 + r) * 256 + h * 32 + seg * 8;
        *(float4*)(sQh + r * 40 + seg * 8) = *(const float4*)(Qh_ + g);
        *(float4*)(sQl + r * 40 + seg * 8) = *(const float4*)(Ql_ + g);
    }
    __syncthreads();

    // Q fragments (regs, reused all tiles)
    uint32_t qfh[2][4], qfl[2][4];
    {
        int mrow = (lane & 7) + 8 * ((lane >> 3) & 1);
        int koff = 8 * (lane >> 4);
#pragma unroll
        for (int kj = 0; kj < 2; kj++) {
            LDSM_X4(qfh[kj], smem_u32(sQh + (w * 16 + mrow) * 40 + kj * 16 + koff));
            LDSM_X4(qfl[kj], smem_u32(sQl + (w * 16 + mrow) * 40 + kj * 16 + koff));
        }
    }

    float m_[2] = {-1e30f, -1e30f}, l_[2] = {0.f, 0.f};
    float o[8][4] = {};

    for (int j = 0; j < ntiles; j++) {
        if (j > 0) __syncthreads();            // stage (j+1)&1 free of readers
        if (j + 1 < ntiles) { issueKV(j + 1); CP_WAIT1; }
        else                { CP_WAIT0; }
        __syncthreads();

        __nv_bfloat16* sKh = stage0 + (j & 1) * ASTAGE;
        __nv_bfloat16* sKl = sKh + AK_E;
        __nv_bfloat16* sVh = sKl + AK_E;
        __nv_bfloat16* sVl = sVh + AV_E;
        int k0 = j * 64;

        // S = Q K^T
        float s[8][4] = {};
        {
            int nrow = (lane & 7) + 8 * (lane >> 4);
            int koff = 8 * ((lane >> 3) & 1);
#pragma unroll
            for (int kj = 0; kj < 2; kj++) {
#pragma unroll
                for (int p = 0; p < 4; p++) {
                    uint32_t kb_h[4], kb_l[4];
                    LDSM_X4(kb_h, smem_u32(sKh + (p * 16 + nrow) * 40 + kj * 16 + koff));
                    LDSM_X4(kb_l, smem_u32(sKl + (p * 16 + nrow) * 40 + kj * 16 + koff));
                    MMA_BF16(s[2 * p],     qfh[kj], kb_h);
                    MMA_BF16(s[2 * p],     qfh[kj], kb_l);
                    MMA_BF16(s[2 * p],     qfl[kj], kb_h);
                    MMA_BF16(s[2 * p + 1], qfh[kj], kb_h + 2);
                    MMA_BF16(s[2 * p + 1], qfh[kj], kb_l + 2);
                    MMA_BF16(s[2 * p + 1], qfl[kj], kb_h + 2);
                }
            }
        }

        // causal mask
        if (k0 + 63 > rw) {
#pragma unroll
            for (int nt = 0; nt < 8; nt++)
#pragma unroll
                for (int e = 0; e < 4; e++) {
                    int col = k0 + nt * 8 + (lane & 3) * 2 + (e & 1);
                    int row = rw + (lane >> 2) + (e >> 1) * 8;
                    if (col > row) s[nt][e] = -1e30f;
                }
        }

        // online softmax (quad reductions)
        float alpha[2];
#pragma unroll
        for (int half = 0; half < 2; half++) {
            float mx = -1e30f;
#pragma unroll
            for (int nt = 0; nt < 8; nt++)
                mx = fmaxf(mx, fmaxf(s[nt][2 * half], s[nt][2 * half + 1]));
            mx = fmaxf(mx, __shfl_xor_sync(0xffffffffu, mx, 1));
            mx = fmaxf(mx, __shfl_xor_sync(0xffffffffu, mx, 2));
            float mnew = fmaxf(m_[half], mx);
            alpha[half] = __expf(m_[half] - mnew);
            m_[half] = mnew;
            float sum = 0.f;
#pragma unroll
            for (int nt = 0; nt < 8; nt++) {
                s[nt][2 * half]     = __expf(s[nt][2 * half] - mnew);
                s[nt][2 * half + 1] = __expf(s[nt][2 * half + 1] - mnew);
                sum += s[nt][2 * half] + s[nt][2 * half + 1];
            }
            sum += __shfl_xor_sync(0xffffffffu, sum, 1);
            sum += __shfl_xor_sync(0xffffffffu, sum, 2);
            l_[half] = l_[half] * alpha[half] + sum;
        }
#pragma unroll
        for (int dt = 0; dt < 8; dt++) {
            o[dt][0] *= alpha[0]; o[dt][1] *= alpha[0];
            o[dt][2] *= alpha[1]; o[dt][3] *= alpha[1];
        }

        // pack P fragments (C-frag -> A-frag identity)
        uint32_t pah[4][4], pal[4][4];
#pragma unroll
        for (int kj = 0; kj < 4; kj++) {
            packhl(s[2 * kj][0],     s[2 * kj][1],     pah[kj][0], pal[kj][0]);
            packhl(s[2 * kj][2],     s[2 * kj][3],     pah[kj][1], pal[kj][1]);
            packhl(s[2 * kj + 1][0], s[2 * kj + 1][1], pah[kj][2], pal[kj][2]);
            packhl(s[2 * kj + 1][2], s[2 * kj + 1][3], pah[kj][3], pal[kj][3]);
        }

        // O += P V  (V via ldmatrix.trans)
        {
            int vrow = lane & 15;
            int vcol = 8 * (lane >> 4);
#pragma unroll
            for (int kj = 0; kj < 4; kj++) {
#pragma unroll
                for (int p = 0; p < 4; p++) {
                    uint32_t vb_h[4], vb_l[4];
                    LDSM_X4_T(vb_h, smem_u32(sVh + (kj * 16 + vrow) * 72 + p * 16 + vcol));
                    LDSM_X4_T(vb_l, smem_u32(sVl + (kj * 16 + vrow) * 72 + p * 16 + vcol));
                    MMA_BF16(o[2 * p],     pah[kj], vb_h);
                    MMA_BF16(o[2 * p],     pah[kj], vb_l);
                    MMA_BF16(o[2 * p],     pal[kj], vb_h);
                    MMA_BF16(o[2 * p + 1], pah[kj], vb_h + 2);
                    MMA_BF16(o[2 * p + 1], pah[kj], vb_l + 2);
                    MMA_BF16(o[2 * p + 1], pal[kj], vb_h + 2);
                }
            }
        }
    }

    // epilogue: self-align removal + 1/l + hilo write
#pragma unroll
    for (int half = 0; half < 2; half++) {
        int row = rw + (lane >> 2) + half * 8;
        float dp = 0.f, nn = 0.f;
        float vv[8][2];
#pragma unroll
        for (int dt = 0; dt < 8; dt++) {
            int c0 = dt * 8 + (lane & 3) * 2;
            size_t g = (hb + row) * 512 + h * 64 + c0;
            __nv_bfloat162 th = *(const __nv_bfloat162*)(Vh_ + g);
            __nv_bfloat162 tl = *(const __nv_bfloat162*)(Vl_ + g);
            float v0 = __bfloat162float(th.x) + __bfloat162float(tl.x);
            float v1 = __bfloat162float(th.y) + __bfloat162float(tl.y);
            vv[dt][0] = v0; vv[dt][1] = v1;
            dp += o[dt][2 * half] * v0 + o[dt][2 * half + 1] * v1;
            nn += v0 * v0 + v1 * v1;
        }
        dp += __shfl_xor_sync(0xffffffffu, dp, 1);
        dp += __shfl_xor_sync(0xffffffffu, dp, 2);
        nn += __shfl_xor_sync(0xffffffffu, nn, 1);
        nn += __shfl_xor_sync(0xffffffffu, nn, 2);
        float coef = dp / fmaxf(nn, 1e-24f);
        float linv = 1.0f / l_[half];
#pragma unroll
        for (int dt = 0; dt < 8; dt++) {
            int c0 = dt * 8 + (lane & 3) * 2;
            size_t g = (hb + row) * 512 + h * 64 + c0;
            float y0 = (o[dt][2 * half]     - coef * vv[dt][0]) * linv;
            float y1 = (o[dt][2 * half + 1] - coef * vv[dt][1]) * linv;
            uint32_t ph, pl;
            packhl(y0, y1, ph, pl);
            *(uint32_t*)(yh + g) = ph;
            *(uint32_t*)(yl + g) = pl;
        }
    }
}

// ---------------- layernorm -> bf16 hi/lo ----------------
__global__ void ln_hilo(const float* __restrict__ in, const float* __restrict__ g,
                        const float* __restrict__ bta,
                        __nv_bfloat16* __restrict__ oh, __nv_bfloat16* __restrict__ ol) {
    int row = blockIdx.x * 8 + (threadIdx.x >> 5);
    int lane = threadIdx.x & 31;
    const float* p = in + (size_t)row * 512;
    float v[16];
    float s = 0.f;
#pragma unroll
    for (int j = 0; j < 16; j++) { v[j] = p[lane + 32 * j]; s += v[j]; }
#pragma unroll
    for (int off = 16; off; off >>= 1) s += __shfl_xor_sync(0xffffffffu, s, off);
    float mean = s * (1.0f / 512.0f);
    float s2 = 0.f;
#pragma unroll
    for (int j = 0; j < 16; j++) { float d = v[j] - mean; s2 += d * d; }
#pragma unroll
    for (int off = 16; off; off >>= 1) s2 += __shfl_xor_sync(0xffffffffu, s2, off);
    float r = rsqrtf(s2 * (1.0f / 512.0f) + 1e-5f);
#pragma unroll
    for (int j = 0; j < 16; j++) {
        int c = lane + 32 * j;
        float ov = (v[j] - mean) * r * g[c] + bta[c];
        __nv_bfloat16 hx, lx;
        hilo(ov, hx, lx);
        oh[(size_t)row * 512 + c] = hx;
        ol[(size_t)row * 512 + c] = lx;
    }
}

// ---------------- RMS norm -> bf16 hi/lo ----------------
__global__ void rms_hilo(const float* __restrict__ in,
                         __nv_bfloat16* __restrict__ oh, __nv_bfloat16* __restrict__ ol) {
    int row = blockIdx.x * 8 + (threadIdx.x >> 5);
    int lane = threadIdx.x & 31;
    const float* p = in + (size_t)row * 512;
    float v[16];
    float s2 = 0.f;
#pragma unroll
    for (int j = 0; j < 16; j++) { v[j] = p[lane + 32 * j]; s2 += v[j] * v[j]; }
#pragma unroll
    for (int off = 16; off; off >>= 1) s2 += __shfl_xor_sync(0xffffffffu, s2, off);
    float r = rsqrtf(s2 * (1.0f / 512.0f) + 1e-6f);
#pragma unroll
    for (int j = 0; j < 16; j++) {
        float ov = v[j] * r;
        __nv_bfloat16 hx, lx;
        hilo(ov, hx, lx);
        oh[(size_t)row * 512 + lane + 32 * j] = hx;
        ol[(size_t)row * 512 + lane + 32 * j] = lx;
    }
}

// ---------------- launch ----------------
extern "C" void kernel_launch(void* const* d_in, const int* in_sizes, int n_in,
                              void* d_out, int out_size) {
    const float* x      = (const float*)d_in[0];
    const float* qp     = (const float*)d_in[1];
    const float* kp     = (const float*)d_in[2];
    const float* wv     = (const float*)d_in[3];
    const float* wproj  = (const float*)d_in[4];
    const float* qg     = (const float*)d_in[5];
    const float* ew0    = (const float*)d_in[6];
    const float* g1     = (const float*)d_in[7];
    const float* b1     = (const float*)d_in[8];
    const float* ew1    = (const float*)d_in[9];
    const float* g2     = (const float*)d_in[10];
    const float* b2     = (const float*)d_in[11];
    const float* ew2    = (const float*)d_in[12];
    const float* ewout  = (const float*)d_in[13];
    const float* ctemp  = (const float*)d_in[14];
    float* out = (float*)d_out;

    float *hb, *t1, *t2, *t3, *rope;
    __nv_bfloat16 *A0h, *A0l, *A1h, *A1l, *Wh, *Wl, *Qh, *Ql, *Kh, *Kl, *Vh, *Vl;
    cudaGetSymbolAddress((void**)&hb,  g_h);
    cudaGetSymbolAddress((void**)&t1,  g_t1);
    cudaGetSymbolAddress((void**)&t2,  g_t2);
    cudaGetSymbolAddress((void**)&t3,  g_t3);
    cudaGetSymbolAddress((void**)&rope, g_rope);
    cudaGetSymbolAddress((void**)&A0h, g_A0h);
    cudaGetSymbolAddress((void**)&A0l, g_A0l);
    cudaGetSymbolAddress((void**)&A1h, g_A1h);
    cudaGetSymbolAddress((void**)&A1l, g_A1l);
    cudaGetSymbolAddress((void**)&Wh,  g_Wh);
    cudaGetSymbolAddress((void**)&Wl,  g_Wl);
    cudaGetSymbolAddress((void**)&Qh,  g_Qh);
    cudaGetSymbolAddress((void**)&Ql,  g_Ql);
    cudaGetSymbolAddress((void**)&Kh,  g_Kh);
    cudaGetSymbolAddress((void**)&Kl,  g_Kl);
    cudaGetSymbolAddress((void**)&Vh,  g_Vh);
    cudaGetSymbolAddress((void**)&Vl,  g_Vl);

    cudaFuncSetAttribute(attn_mma, cudaFuncAttributeMaxDynamicSharedMemorySize, ATTN_SMEM);
    cudaFuncSetAttribute(mma_gemm<0, 0>, cudaFuncAttributeMaxDynamicSharedMemorySize, GEMM_SMEM);
    cudaFuncSetAttribute(mma_gemm<0, 2>, cudaFuncAttributeMaxDynamicSharedMemorySize, GEMM_SMEM);
    cudaFuncSetAttribute(mma_gemm<1, 1>, cudaFuncAttributeMaxDynamicSharedMemorySize, GEMM_SMEM);
    cudaFuncSetAttribute(mma_gemm<2, 0>, cudaFuncAttributeMaxDynamicSharedMemorySize, GEMM_SMEM);
    cudaFuncSetAttribute(mma_gemm<3, 0>, cudaFuncAttributeMaxDynamicSharedMemorySize, GEMM_SMEM);

    // 0. fused prep: all weights hilo + x hilo + rope table
    prep_kernel<<<14528, 256>>>(x, qp, kp, wv, wproj, ew0, ew1, ew2, ewout,
                                Wh, Wl, A0h, A0l, rope);
    // 1. QKV GEMM with fused RoPE epilogue -> Q/K/V hilo directly
    mma_gemm<0, 2><<<dim3(8, 32), 256, GEMM_SMEM>>>(A0h, A0l, Wh, Wl, nullptr, nullptr,
                                                    1024, 1024, nullptr, Vh, Vl,
                                                    Qh, Ql, Kh, Kl, rope, qg);
    // 2. HMMA flash attention -> A1 hilo
    attn_mma<<<dim3(16, 8, 2), 256, ATTN_SMEM>>>(Qh, Ql, Kh, Kl, Vh, Vl, A1h, A1l);
    // 3. h = x + y @ wproj^T  (+ hilo(h) -> A0)
    mma_gemm<1, 1><<<dim3(4, 32), 256, GEMM_SMEM>>>(A1h, A1l, Wh + 1024 * 512, Wl + 1024 * 512,
                                                    x, hb, 512, 512, nullptr, A0h, A0l,
                                                    nullptr, nullptr, nullptr, nullptr, nullptr, nullptr);
    // 4. t1 = h @ ew0^T
    mma_gemm<0, 0><<<dim3(4, 32), 256, GEMM_SMEM>>>(A0h, A0l, Wh + 1536 * 512, Wl + 1536 * 512,
                                                    nullptr, t1, 512, 512, nullptr, nullptr, nullptr,
                                                    nullptr, nullptr, nullptr, nullptr, nullptr, nullptr);
    ln_hilo<<<512, 256>>>(t1, g1, b1, A1h, A1l);
    // 5. t3 = h + silu(ln1 @ ew1^T)
    mma_gemm<2, 0><<<dim3(4, 32), 256, GEMM_SMEM>>>(A1h, A1l, Wh + 2048 * 512, Wl + 2048 * 512,
                                                    hb, t3, 512, 512, nullptr, nullptr, nullptr,
                                                    nullptr, nullptr, nullptr, nullptr, nullptr, nullptr);
    ln_hilo<<<512, 256>>>(t3, g2, b2, A0h, A0l);
    // 6. t2 = t3 + silu(ln2 @ ew2^T)
    mma_gemm<2, 0><<<dim3(4, 32), 256, GEMM_SMEM>>>(A0h, A0l, Wh + 2560 * 512, Wl + 2560 * 512,
                                                    t3, t2, 512, 512, nullptr, nullptr, nullptr,
                                                    nullptr, nullptr, nullptr, nullptr, nullptr, nullptr);
    // 7. rms + head
    rms_hilo<<<512, 256>>>(t2, A1h, A1l);
    mma_gemm<3, 0><<<dim3(1, 32), 256, GEMM_SMEM>>>(A1h, A1l, Wh + 3072 * 512, Wl + 3072 * 512,
                                                    nullptr, out, 32, 32, ctemp, nullptr, nullptr,
                                                    nullptr, nullptr, nullptr, nullptr, nullptr, nullptr);
}

// round 11
// speedup vs baseline: 3.2895x; 1.0040x over previous
#include <cuda_runtime.h>
#include <cuda_bf16.h>
#include <math.h>
#include <math_constants.h>
#include <cstdint>

#define T_LEN 2048

// ---------------- scratch (no allocations allowed) ----------------
__device__ float g_h [4096 * 512];
__device__ float g_t1[4096 * 512];
__device__ float g_t2[4096 * 512];
__device__ float g_t3[4096 * 512];
__device__ float g_rope[2048 * 16 * 2];
__device__ __nv_bfloat16 g_A0h[4096 * 512], g_A0l[4096 * 512];
__device__ __nv_bfloat16 g_A1h[4096 * 512], g_A1l[4096 * 512];
__device__ __nv_bfloat16 g_Qh[4096 * 256], g_Ql[4096 * 256];
__device__ __nv_bfloat16 g_Kh[4096 * 256], g_Kl[4096 * 256];
__device__ __nv_bfloat16 g_Vh[4096 * 512], g_Vl[4096 * 512];
// weight rows: [0:1024) qkv | [1024:1536) wproj | [1536:2048) ew0 | [2048:2560) ew1 | [2560:3072) ew2 | [3072:3104) ewout
__device__ __nv_bfloat16 g_Wh[3104 * 512], g_Wl[3104 * 512];

// ---------------- helpers ----------------
static __device__ __forceinline__ uint32_t smem_u32(const void* p) {
    uint32_t a;
    asm("{ .reg .u64 t; cvta.to.shared.u64 t, %1; cvt.u32.u64 %0, t; }" : "=r"(a) : "l"(p));
    return a;
}
static __device__ __forceinline__ void hilo(float v, __nv_bfloat16& h, __nv_bfloat16& l) {
    h = __float2bfloat16(v);
    l = __float2bfloat16(v - __bfloat162float(h));
}
static __device__ __forceinline__ void packhl(float a, float b, uint32_t& ph, uint32_t& pl) {
    __nv_bfloat162 hp, lp;
    hp.x = __float2bfloat16(a);
    hp.y = __float2bfloat16(b);
    lp.x = __float2bfloat16(a - __bfloat162float(hp.x));
    lp.y = __float2bfloat16(b - __bfloat162float(hp.y));
    ph = *(uint32_t*)&hp;
    pl = *(uint32_t*)&lp;
}

#define LDSM_X4(r, a)                                                          \
    asm volatile("ldmatrix.sync.aligned.m8n8.x4.shared.b16 {%0,%1,%2,%3}, [%4];" \
        : "=r"((r)[0]), "=r"((r)[1]), "=r"((r)[2]), "=r"((r)[3]) : "r"(a))
#define LDSM_X4_T(r, a)                                                        \
    asm volatile("ldmatrix.sync.aligned.m8n8.x4.trans.shared.b16 {%0,%1,%2,%3}, [%4];" \
        : "=r"((r)[0]), "=r"((r)[1]), "=r"((r)[2]), "=r"((r)[3]) : "r"(a))
#define MMA_BF16(d, A, B)                                                      \
    asm volatile("mma.sync.aligned.m16n8k16.row.col.f32.bf16.bf16.f32 "        \
        "{%0,%1,%2,%3}, {%4,%5,%6,%7}, {%8,%9}, {%0,%1,%2,%3};"                \
        : "+f"((d)[0]), "+f"((d)[1]), "+f"((d)[2]), "+f"((d)[3])               \
        : "r"((A)[0]), "r"((A)[1]), "r"((A)[2]), "r"((A)[3]),                  \
          "r"((B)[0]), "r"((B)[1]))
#define CPA(dst, src, sz) \
    asm volatile("cp.async.ca.shared.global [%0], [%1], 16, %2;" :: "r"(dst), "l"(src), "r"(sz))
#define CP_COMMIT asm volatile("cp.async.commit_group;" ::: "memory")
#define CP_WAIT0  asm volatile("cp.async.wait_group 0;" ::: "memory")
#define CP_WAIT1  asm volatile("cp.async.wait_group 1;" ::: "memory")

// ---------------- fused prep: weights hilo + x hilo + rope table ----------------
__global__ void prep_kernel(
    const float* __restrict__ x, const float* __restrict__ qp, const float* __restrict__ kp,
    const float* __restrict__ wv, const float* __restrict__ wproj,
    const float* __restrict__ ew0, const float* __restrict__ ew1,
    const float* __restrict__ ew2, const float* __restrict__ ewout,
    __nv_bfloat16* __restrict__ Wh, __nv_bfloat16* __restrict__ Wl,
    __nv_bfloat16* __restrict__ A0h, __nv_bfloat16* __restrict__ A0l,
    float* __restrict__ rope)
{
    int idx = blockIdx.x * blockDim.x + threadIdx.x;
    if (idx < 524288) {
        int n = idx >> 9, d = idx & 511;
        float v;
        if (n < 256) v = qp[((n >> 5) * 512 + d) * 32 + (n & 31)];
        else if (n < 512) { int nn = n - 256; v = kp[((nn >> 5) * 512 + d) * 32 + (nn & 31)]; }
        else v = wv[(size_t)(n - 512) * 512 + d];
        hilo(v, Wh[idx], Wl[idx]);
    } else if (idx < 786432) {
        int i = idx - 524288;
        hilo(wproj[i], Wh[1024 * 512 + i], Wl[1024 * 512 + i]);
    } else if (idx < 1048576) {
        int i = idx - 786432;
        hilo(ew0[i], Wh[1536 * 512 + i], Wl[1536 * 512 + i]);
    } else if (idx < 1310720) {
        int i = idx - 1048576;
        hilo(ew1[i], Wh[2048 * 512 + i], Wl[2048 * 512 + i]);
    } else if (idx < 1572864) {
        int i = idx - 1310720;
        hilo(ew2[i], Wh[2560 * 512 + i], Wl[2560 * 512 + i]);
    } else if (idx < 1589248) {
        int i = idx - 1572864;
        hilo(ewout[i], Wh[3072 * 512 + i], Wl[3072 * 512 + i]);
    } else if (idx < 3686400) {
        int i = idx - 1589248;
        hilo(x[i], A0h[i], A0l[i]);
    } else if (idx < 3719168) {
        int i2 = idx - 3686400;       // t*16 + i
        int t = i2 >> 4, i = i2 & 15;
        double fd = pow(10000.0, -(double)(2 * i) / 32.0);
        float ang = (float)t * (float)fd;
        double ad = (double)ang;
        rope[i2 * 2]     = (float)cos(ad);
        rope[i2 * 2 + 1] = (float)sin(ad);
    }
}

// ---------------- HMMA bf16x3 GEMM, tile 128x64, 2 CTAs/SM, cp.async 2-stage ----------------
// D[m][n] = sum_k A[m][k]*B[n][k], K=512, 8 warps as 4m x 2n (warp tile 32x32).
// EPI: 0 none, 1 res+acc, 2 res+silu(acc), 3 tanh(acc/(softplus(extra[n])+1e-4))
// OMODE: 0 none, 1 full hilo out, 2 QKV fused epilogue (rope for n<512, V hilo for n>=512)
#define PAD 72
#define ARRA (128 * PAD)
#define ARRB (64 * PAD)
#define STAGE_E (2 * ARRA + 2 * ARRB)       // 27648 elems
#define STAGEB (STAGE_E * 2)                // 55296 bytes
#define GEMM_SMEM (2 * STAGEB)              // 110592 bytes
template <int EPI, int OMODE>
__global__ void __launch_bounds__(256, 2) mma_gemm(
    const __nv_bfloat16* __restrict__ Ah, const __nv_bfloat16* __restrict__ Al,
    const __nv_bfloat16* __restrict__ Bh, const __nv_bfloat16* __restrict__ Bl,
    const float* __restrict__ Res, float* __restrict__ C,
    int Ntot, int NtotB, const float* __restrict__ extra,
    __nv_bfloat16* __restrict__ Oh, __nv_bfloat16* __restrict__ Ol,
    __nv_bfloat16* __restrict__ Qh, __nv_bfloat16* __restrict__ Ql,
    __nv_bfloat16* __restrict__ Kh, __nv_bfloat16* __restrict__ Kl,
    const float* __restrict__ rope_tab, const float* __restrict__ qgain)
{
    extern __shared__ __nv_bfloat16 smb[];
    uint32_t sbase = smem_u32(smb);

    int tid = threadIdx.x, lane = tid & 31, wid = tid >> 5;
    int warp_m = wid & 3, warp_n = wid >> 2;
    int m0 = blockIdx.y * 128, n0 = blockIdx.x * 64;

    uint32_t a_row = warp_m * 32 + (lane & 15);
    uint32_t a_ko  = (lane >> 4) * 8;
    uint32_t b_row = warp_n * 32 + (lane & 7);
    uint32_t b_ko  = ((lane >> 3) & 1) * 8;

    float acc[2][4][4] = {};

    auto issue = [&](int c) {
        uint32_t st = (uint32_t)(c & 1) * STAGEB;
        int k0c = c * 64;
#pragma unroll
        for (int t = 0; t < 4; t++) {     // A: 128 rows x 8 segs
            int idx = tid + t * 256;
            int r = idx >> 3, q = idx & 7;
            uint32_t so = st + (uint32_t)(r * PAD + q * 8) * 2;
            size_t g = (size_t)(m0 + r) * 512 + k0c + q * 8;
            CPA(sbase + so,             Ah + g, 16);
            CPA(sbase + so + ARRA * 2,  Al + g, 16);
        }
#pragma unroll
        for (int t = 0; t < 2; t++) {     // B: 64 rows x 8 segs
            int idx = tid + t * 256;
            int r = idx >> 3, q = idx & 7;
            uint32_t so = st + (uint32_t)(2 * ARRA + r * PAD + q * 8) * 2;
            int n = n0 + r;
            int ok = (n < NtotB) ? 16 : 0;
            size_t g = (size_t)(ok ? n : 0) * 512 + k0c + q * 8;
            CPA(sbase + so,             Bh + g, ok);
            CPA(sbase + so + ARRB * 2,  Bl + g, ok);
        }
        CP_COMMIT;
    };

    issue(0);
    for (int c = 0; c < 8; c++) {
        CP_WAIT0;
        __syncthreads();
        if (c < 7) issue(c + 1);

        uint32_t st = (uint32_t)(c & 1) * STAGEB;
        uint32_t uAh = sbase + st;
        uint32_t uAl = uAh + ARRA * 2;
        uint32_t uBh = uAl + ARRA * 2;
        uint32_t uBl = uBh + ARRB * 2;

#pragma unroll
        for (int kk = 0; kk < 4; kk++) {
            uint32_t bh[4][2], bl[4][2];
#pragma unroll
            for (int ni = 0; ni < 4; ni++) {
                uint32_t off = ((b_row + ni * 8) * PAD + kk * 16 + b_ko) * 2;
                asm volatile("ldmatrix.sync.aligned.m8n8.x2.shared.b16 {%0,%1}, [%2];"
                    : "=r"(bh[ni][0]), "=r"(bh[ni][1]) : "r"(uBh + off));
                asm volatile("ldmatrix.sync.aligned.m8n8.x2.shared.b16 {%0,%1}, [%2];"
                    : "=r"(bl[ni][0]), "=r"(bl[ni][1]) : "r"(uBl + off));
            }
#pragma unroll
            for (int mi = 0; mi < 2; mi++) {
                uint32_t ah[4], al[4];
                uint32_t off = ((a_row + mi * 16) * PAD + kk * 16 + a_ko) * 2;
                LDSM_X4(ah, uAh + off);
                LDSM_X4(al, uAl + off);
#pragma unroll
                for (int ni = 0; ni < 4; ni++) {
                    MMA_BF16(acc[mi][ni], ah, bh[ni]);
                    MMA_BF16(acc[mi][ni], ah, bl[ni]);
                    MMA_BF16(acc[mi][ni], al, bh[ni]);
                }
            }
        }
        __syncthreads();
    }

    // epilogue
    int gid = lane >> 2, tig = lane & 3;

    if (OMODE == 2) {
        int colbase = n0 + warp_n * 32;   // warp-uniform, one 32-col head group
        if (colbase < 512) {
            // q/k region: rope rotate in-register, pairs (ni, ni+2)
            int which = colbase >= 256;
            int hh = (colbase >> 5) & 7;
            float scale = which ? 1.0f : (qgain[hh] * 0.17677669529663687f);
            __nv_bfloat16* dh = which ? Kh : Qh;
            __nv_bfloat16* dl = which ? Kl : Ql;
            int off0 = colbase & 255;
#pragma unroll
            for (int mi = 0; mi < 2; mi++) {
#pragma unroll
                for (int half = 0; half < 2; half++) {
                    int m = m0 + warp_m * 32 + mi * 16 + gid + half * 8;
                    int t = m & (T_LEN - 1);
#pragma unroll
                    for (int ni = 0; ni < 2; ni++) {
#pragma unroll
                        for (int e = 0; e < 2; e++) {
                            int i = ni * 8 + tig * 2 + e;
                            float x1 = acc[mi][ni][half * 2 + e];
                            float x2 = acc[mi][ni + 2][half * 2 + e];
                            float cth = rope_tab[(t * 16 + i) * 2];
                            float sth = rope_tab[(t * 16 + i) * 2 + 1];
                            float o1 = (x1 * cth - x2 * sth) * scale;
                            float o2 = (x2 * cth + x1 * sth) * scale;
                            __nv_bfloat16 h1, l1, h2, l2;
                            hilo(o1, h1, l1); hilo(o2, h2, l2);
                            size_t base = (size_t)m * 256 + off0 + i;
                            dh[base] = h1;      dl[base] = l1;
                            dh[base + 16] = h2; dl[base + 16] = l2;
                        }
                    }
                }
            }
        } else {
            // V region: hilo split
#pragma unroll
            for (int mi = 0; mi < 2; mi++) {
#pragma unroll
                for (int ni = 0; ni < 4; ni++) {
#pragma unroll
                    for (int half = 0; half < 2; half++) {
                        int m = m0 + warp_m * 32 + mi * 16 + gid + half * 8;
                        int nb = colbase + ni * 8 + tig * 2;
#pragma unroll
                        for (int e = 0; e < 2; e++) {
                            int n = nb + e;
                            __nv_bfloat16 hx, lx;
                            hilo(acc[mi][ni][half * 2 + e], hx, lx);
                            Oh[(size_t)m * 512 + (n - 512)] = hx;
                            Ol[(size_t)m * 512 + (n - 512)] = lx;
                        }
                    }
                }
            }
        }
        return;
    }

#pragma unroll
    for (int mi = 0; mi < 2; mi++) {
#pragma unroll
        for (int ni = 0; ni < 4; ni++) {
#pragma unroll
            for (int half = 0; half < 2; half++) {
                int m = m0 + warp_m * 32 + mi * 16 + gid + half * 8;
                int nbase = n0 + warp_n * 32 + ni * 8 + tig * 2;
#pragma unroll
                for (int e = 0; e < 2; e++) {
                    int n = nbase + e;
                    if (n >= Ntot) continue;
                    float v = acc[mi][ni][half * 2 + e];
                    if (EPI == 1) {
                        v += Res[(size_t)m * Ntot + n];
                    } else if (EPI == 2) {
                        float sg = 1.0f / (1.0f + __expf(-v));
                        v = Res[(size_t)m * Ntot + n] + v * sg;
                    } else if (EPI == 3) {
                        float ct = extra[n];
                        float sp = (ct > 20.0f) ? ct : log1pf(__expf(ct));
                        v = tanhf(v / (sp + 1e-4f));
                    }
                    C[(size_t)m * Ntot + n] = v;
                    if (OMODE == 1) {
                        __nv_bfloat16 hx, lx;
                        hilo(v, hx, lx);
                        Oh[(size_t)m * 512 + n] = hx;
                        Ol[(size_t)m * 512 + n] = lx;
                    }
                }
            }
        }
    }
}

// ---------------- HMMA flash attention + self-align, bf16x3, cp.async double-buffered ----------------
// BQ=128 (8 warps), K tiles of 64, 2-stage K/V pipeline. grid (16, 8, 2), 256 thr.
#define AQ_E   (128 * 40)
#define AK_E   (64 * 40)
#define AV_E   (64 * 72)
#define ASTAGE (2 * AK_E + 2 * AV_E)
#define ATTN_SMEM ((2 * AQ_E + 2 * ASTAGE) * 2)   // 77824 bytes
__global__ void __launch_bounds__(256, 2) attn_mma(
    const __nv_bfloat16* __restrict__ Qh_, const __nv_bfloat16* __restrict__ Ql_,
    const __nv_bfloat16* __restrict__ Kh_, const __nv_bfloat16* __restrict__ Kl_,
    const __nv_bfloat16* __restrict__ Vh_, const __nv_bfloat16* __restrict__ Vl_,
    __nv_bfloat16* __restrict__ yh, __nv_bfloat16* __restrict__ yl)
{
    extern __shared__ __nv_bfloat16 sb[];
    __nv_bfloat16* sQh = sb;
    __nv_bfloat16* sQl = sQh + AQ_E;
    __nv_bfloat16* stage0 = sQl + AQ_E;

    int qb = (int)gridDim.x - 1 - (int)blockIdx.x;
    int h = blockIdx.y, b = blockIdx.z;
    int tid = threadIdx.x, lane = tid & 31, w = tid >> 5;
    int q0 = qb * 128;
    int rw = q0 + w * 16;
    const size_t hb = (size_t)b * T_LEN;
    int ntiles = 2 * qb + 2;

    auto issueKV = [&](int j) {
        int k0 = j * 64;
        uint32_t st = smem_u32(stage0 + (j & 1) * ASTAGE);
        {
            int r = tid >> 2, seg = tid & 3;
            size_t g = (hb + k0 + r) * 256 + h * 32 + seg * 8;
            uint32_t d = st + (uint32_t)(r * 40 + seg * 8) * 2;
            CPA(d,              Kh_ + g, 16);
            CPA(d + AK_E * 2,   Kl_ + g, 16);
        }
#pragma unroll
        for (int t2 = 0; t2 < 2; t2++) {
            int idx = tid + t2 * 256;
            int r = idx >> 3, seg = idx & 7;
            size_t g = (hb + k0 + r) * 512 + h * 64 + seg * 8;
            uint32_t d = st + (uint32_t)(2 * AK_E + r * 72 + seg * 8) * 2;
            CPA(d,              Vh_ + g, 16);
            CPA(d + AV_E * 2,   Vl_ + g, 16);
        }
        CP_COMMIT;
    };

    issueKV(0);

    for (int i = tid; i < 512; i += 256) {
        int r = i >> 2, seg = i & 3;
        size_t g = (hb + q0 + r) * 256 + h * 32 + seg * 8;
        *(float4*)(sQh + r * 40 + seg * 8) = *(const float4*)(Qh_ + g);
        *(float4*)(sQl + r * 40 + seg * 8) = *(const float4*)(Ql_ + g);
    }
    __syncthreads();

    uint32_t qfh[2][4], qfl[2][4];
    {
        int mrow = (lane & 7) + 8 * ((lane >> 3) & 1);
        int koff = 8 * (lane >> 4);
#pragma unroll
        for (int kj = 0; kj < 2; kj++) {
            LDSM_X4(qfh[kj], smem_u32(sQh + (w * 16 + mrow) * 40 + kj * 16 + koff));
            LDSM_X4(qfl[kj], smem_u32(sQl + (w * 16 + mrow) * 40 + kj * 16 + koff));
        }
    }

    float m_[2] = {-1e30f, -1e30f}, l_[2] = {0.f, 0.f};
    float o[8][4] = {};

    for (int j = 0; j < ntiles; j++) {
        if (j > 0) __syncthreads();
        if (j + 1 < ntiles) { issueKV(j + 1); CP_WAIT1; }
        else                { CP_WAIT0; }
        __syncthreads();

        __nv_bfloat16* sKh = stage0 + (j & 1) * ASTAGE;
        __nv_bfloat16* sKl = sKh + AK_E;
        __nv_bfloat16* sVh = sKl + AK_E;
        __nv_bfloat16* sVl = sVh + AV_E;
        int k0 = j * 64;

        float s[8][4] = {};
        {
            int nrow = (lane & 7) + 8 * (lane >> 4);
            int koff = 8 * ((lane >> 3) & 1);
#pragma unroll
            for (int kj = 0; kj < 2; kj++) {
#pragma unroll
                for (int p = 0; p < 4; p++) {
                    uint32_t kb_h[4], kb_l[4];
                    LDSM_X4(kb_h, smem_u32(sKh + (p * 16 + nrow) * 40 + kj * 16 + koff));
                    LDSM_X4(kb_l, smem_u32(sKl + (p * 16 + nrow) * 40 + kj * 16 + koff));
                    MMA_BF16(s[2 * p],     qfh[kj], kb_h);
                    MMA_BF16(s[2 * p],     qfh[kj], kb_l);
                    MMA_BF16(s[2 * p],     qfl[kj], kb_h);
                    MMA_BF16(s[2 * p + 1], qfh[kj], kb_h + 2);
                    MMA_BF16(s[2 * p + 1], qfh[kj], kb_l + 2);
                    MMA_BF16(s[2 * p + 1], qfl[kj], kb_h + 2);
                }
            }
        }

        if (k0 + 63 > rw) {
#pragma unroll
            for (int nt = 0; nt < 8; nt++)
#pragma unroll
                for (int e = 0; e < 4; e++) {
                    int col = k0 + nt * 8 + (lane & 3) * 2 + (e & 1);
                    int row = rw + (lane >> 2) + (e >> 1) * 8;
                    if (col > row) s[nt][e] = -1e30f;
                }
        }

        float alpha[2];
#pragma unroll
        for (int half = 0; half < 2; half++) {
            float mx = -1e30f;
#pragma unroll
            for (int nt = 0; nt < 8; nt++)
                mx = fmaxf(mx, fmaxf(s[nt][2 * half], s[nt][2 * half + 1]));
            mx = fmaxf(mx, __shfl_xor_sync(0xffffffffu, mx, 1));
            mx = fmaxf(mx, __shfl_xor_sync(0xffffffffu, mx, 2));
            float mnew = fmaxf(m_[half], mx);
            alpha[half] = __expf(m_[half] - mnew);
            m_[half] = mnew;
            float sum = 0.f;
#pragma unroll
            for (int nt = 0; nt < 8; nt++) {
                s[nt][2 * half]     = __expf(s[nt][2 * half] - mnew);
                s[nt][2 * half + 1] = __expf(s[nt][2 * half + 1] - mnew);
                sum += s[nt][2 * half] + s[nt][2 * half + 1];
            }
            sum += __shfl_xor_sync(0xffffffffu, sum, 1);
            sum += __shfl_xor_sync(0xffffffffu, sum, 2);
            l_[half] = l_[half] * alpha[half] + sum;
        }
#pragma unroll
        for (int dt = 0; dt < 8; dt++) {
            o[dt][0] *= alpha[0]; o[dt][1] *= alpha[0];
            o[dt][2] *= alpha[1]; o[dt][3] *= alpha[1];
        }

        uint32_t pah[4][4], pal[4][4];
#pragma unroll
        for (int kj = 0; kj < 4; kj++) {
            packhl(s[2 * kj][0],     s[2 * kj][1],     pah[kj][0], pal[kj][0]);
            packhl(s[2 * kj][2],     s[2 * kj][3],     pah[kj][1], pal[kj][1]);
            packhl(s[2 * kj + 1][0], s[2 * kj + 1][1], pah[kj][2], pal[kj][2]);
            packhl(s[2 * kj + 1][2], s[2 * kj + 1][3], pah[kj][3], pal[kj][3]);
        }

        {
            int vrow = lane & 15;
            int vcol = 8 * (lane >> 4);
#pragma unroll
            for (int kj = 0; kj < 4; kj++) {
#pragma unroll
                for (int p = 0; p < 4; p++) {
                    uint32_t vb_h[4], vb_l[4];
                    LDSM_X4_T(vb_h, smem_u32(sVh + (kj * 16 + vrow) * 72 + p * 16 + vcol));
                    LDSM_X4_T(vb_l, smem_u32(sVl + (kj * 16 + vrow) * 72 + p * 16 + vcol));
                    MMA_BF16(o[2 * p],     pah[kj], vb_h);
                    MMA_BF16(o[2 * p],     pah[kj], vb_l);
                    MMA_BF16(o[2 * p],     pal[kj], vb_h);
                    MMA_BF16(o[2 * p + 1], pah[kj], vb_h + 2);
                    MMA_BF16(o[2 * p + 1], pah[kj], vb_l + 2);
                    MMA_BF16(o[2 * p + 1], pal[kj], vb_h + 2);
                }
            }
        }
    }

#pragma unroll
    for (int half = 0; half < 2; half++) {
        int row = rw + (lane >> 2) + half * 8;
        float dp = 0.f, nn = 0.f;
        float vv[8][2];
#pragma unroll
        for (int dt = 0; dt < 8; dt++) {
            int c0 = dt * 8 + (lane & 3) * 2;
            size_t g = (hb + row) * 512 + h * 64 + c0;
            __nv_bfloat162 th = *(const __nv_bfloat162*)(Vh_ + g);
            __nv_bfloat162 tl = *(const __nv_bfloat162*)(Vl_ + g);
            float v0 = __bfloat162float(th.x) + __bfloat162float(tl.x);
            float v1 = __bfloat162float(th.y) + __bfloat162float(tl.y);
            vv[dt][0] = v0; vv[dt][1] = v1;
            dp += o[dt][2 * half] * v0 + o[dt][2 * half + 1] * v1;
            nn += v0 * v0 + v1 * v1;
        }
        dp += __shfl_xor_sync(0xffffffffu, dp, 1);
        dp += __shfl_xor_sync(0xffffffffu, dp, 2);
        nn += __shfl_xor_sync(0xffffffffu, nn, 1);
        nn += __shfl_xor_sync(0xffffffffu, nn, 2);
        float coef = dp / fmaxf(nn, 1e-24f);
        float linv = 1.0f / l_[half];
#pragma unroll
        for (int dt = 0; dt < 8; dt++) {
            int c0 = dt * 8 + (lane & 3) * 2;
            size_t g = (hb + row) * 512 + h * 64 + c0;
            float y0 = (o[dt][2 * half]     - coef * vv[dt][0]) * linv;
            float y1 = (o[dt][2 * half + 1] - coef * vv[dt][1]) * linv;
            uint32_t ph, pl;
            packhl(y0, y1, ph, pl);
            *(uint32_t*)(yh + g) = ph;
            *(uint32_t*)(yl + g) = pl;
        }
    }
}

// ---------------- layernorm -> bf16 hi/lo ----------------
__global__ void ln_hilo(const float* __restrict__ in, const float* __restrict__ g,
                        const float* __restrict__ bta,
                        __nv_bfloat16* __restrict__ oh, __nv_bfloat16* __restrict__ ol) {
    int row = blockIdx.x * 8 + (threadIdx.x >> 5);
    int lane = threadIdx.x & 31;
    const float* p = in + (size_t)row * 512;
    float v[16];
    float s = 0.f;
#pragma unroll
    for (int j = 0; j < 16; j++) { v[j] = p[lane + 32 * j]; s += v[j]; }
#pragma unroll
    for (int off = 16; off; off >>= 1) s += __shfl_xor_sync(0xffffffffu, s, off);
    float mean = s * (1.0f / 512.0f);
    float s2 = 0.f;
#pragma unroll
    for (int j = 0; j < 16; j++) { float d = v[j] - mean; s2 += d * d; }
#pragma unroll
    for (int off = 16; off; off >>= 1) s2 += __shfl_xor_sync(0xffffffffu, s2, off);
    float r = rsqrtf(s2 * (1.0f / 512.0f) + 1e-5f);
#pragma unroll
    for (int j = 0; j < 16; j++) {
        int c = lane + 32 * j;
        float ov = (v[j] - mean) * r * g[c] + bta[c];
        __nv_bfloat16 hx, lx;
        hilo(ov, hx, lx);
        oh[(size_t)row * 512 + c] = hx;
        ol[(size_t)row * 512 + c] = lx;
    }
}

// ---------------- RMS norm -> bf16 hi/lo ----------------
__global__ void rms_hilo(const float* __restrict__ in,
                         __nv_bfloat16* __restrict__ oh, __nv_bfloat16* __restrict__ ol) {
    int row = blockIdx.x * 8 + (threadIdx.x >> 5);
    int lane = threadIdx.x & 31;
    const float* p = in + (size_t)row * 512;
    float v[16];
    float s2 = 0.f;
#pragma unroll
    for (int j = 0; j < 16; j++) { v[j] = p[lane + 32 * j]; s2 += v[j] * v[j]; }
#pragma unroll
    for (int off = 16; off; off >>= 1) s2 += __shfl_xor_sync(0xffffffffu, s2, off);
    float r = rsqrtf(s2 * (1.0f / 512.0f) + 1e-6f);
#pragma unroll
    for (int j = 0; j < 16; j++) {
        float ov = v[j] * r;
        __nv_bfloat16 hx, lx;
        hilo(ov, hx, lx);
        oh[(size_t)row * 512 + lane + 32 * j] = hx;
        ol[(size_t)row * 512 + lane + 32 * j] = lx;
    }
}

// ---------------- launch ----------------
extern "C" void kernel_launch(void* const* d_in, const int* in_sizes, int n_in,
                              void* d_out, int out_size) {
    const float* x      = (const float*)d_in[0];
    const float* qp     = (const float*)d_in[1];
    const float* kp     = (const float*)d_in[2];
    const float* wv     = (const float*)d_in[3];
    const float* wproj  = (const float*)d_in[4];
    const float* qg     = (const float*)d_in[5];
    const float* ew0    = (const float*)d_in[6];
    const float* g1     = (const float*)d_in[7];
    const float* b1     = (const float*)d_in[8];
    const float* ew1    = (const float*)d_in[9];
    const float* g2     = (const float*)d_in[10];
    const float* b2     = (const float*)d_in[11];
    const float* ew2    = (const float*)d_in[12];
    const float* ewout  = (const float*)d_in[13];
    const float* ctemp  = (const float*)d_in[14];
    float* out = (float*)d_out;

    float *hb, *t1, *t2, *t3, *rope;
    __nv_bfloat16 *A0h, *A0l, *A1h, *A1l, *Wh, *Wl, *Qh, *Ql, *Kh, *Kl, *Vh, *Vl;
    cudaGetSymbolAddress((void**)&hb,  g_h);
    cudaGetSymbolAddress((void**)&t1,  g_t1);
    cudaGetSymbolAddress((void**)&t2,  g_t2);
    cudaGetSymbolAddress((void**)&t3,  g_t3);
    cudaGetSymbolAddress((void**)&rope, g_rope);
    cudaGetSymbolAddress((void**)&A0h, g_A0h);
    cudaGetSymbolAddress((void**)&A0l, g_A0l);
    cudaGetSymbolAddress((void**)&A1h, g_A1h);
    cudaGetSymbolAddress((void**)&A1l, g_A1l);
    cudaGetSymbolAddress((void**)&Wh,  g_Wh);
    cudaGetSymbolAddress((void**)&Wl,  g_Wl);
    cudaGetSymbolAddress((void**)&Qh,  g_Qh);
    cudaGetSymbolAddress((void**)&Ql,  g_Ql);
    cudaGetSymbolAddress((void**)&Kh,  g_Kh);
    cudaGetSymbolAddress((void**)&Kl,  g_Kl);
    cudaGetSymbolAddress((void**)&Vh,  g_Vh);
    cudaGetSymbolAddress((void**)&Vl,  g_Vl);

    cudaFuncSetAttribute(attn_mma, cudaFuncAttributeMaxDynamicSharedMemorySize, ATTN_SMEM);
    cudaFuncSetAttribute(mma_gemm<0, 0>, cudaFuncAttributeMaxDynamicSharedMemorySize, GEMM_SMEM);
    cudaFuncSetAttribute(mma_gemm<0, 2>, cudaFuncAttributeMaxDynamicSharedMemorySize, GEMM_SMEM);
    cudaFuncSetAttribute(mma_gemm<1, 1>, cudaFuncAttributeMaxDynamicSharedMemorySize, GEMM_SMEM);
    cudaFuncSetAttribute(mma_gemm<2, 0>, cudaFuncAttributeMaxDynamicSharedMemorySize, GEMM_SMEM);
    cudaFuncSetAttribute(mma_gemm<3, 0>, cudaFuncAttributeMaxDynamicSharedMemorySize, GEMM_SMEM);

    // 0. fused prep: all weights hilo + x hilo + rope table
    prep_kernel<<<14528, 256>>>(x, qp, kp, wv, wproj, ew0, ew1, ew2, ewout,
                                Wh, Wl, A0h, A0l, rope);
    // 1. QKV GEMM with fused RoPE epilogue -> Q/K/V hilo directly
    mma_gemm<0, 2><<<dim3(16, 32), 256, GEMM_SMEM>>>(A0h, A0l, Wh, Wl, nullptr, nullptr,
                                                     1024, 1024, nullptr, Vh, Vl,
                                                     Qh, Ql, Kh, Kl, rope, qg);
    // 2. HMMA flash attention -> A1 hilo
    attn_mma<<<dim3(16, 8, 2), 256, ATTN_SMEM>>>(Qh, Ql, Kh, Kl, Vh, Vl, A1h, A1l);
    // 3. h = x + y @ wproj^T  (+ hilo(h) -> A0)
    mma_gemm<1, 1><<<dim3(8, 32), 256, GEMM_SMEM>>>(A1h, A1l, Wh + 1024 * 512, Wl + 1024 * 512,
                                                    x, hb, 512, 512, nullptr, A0h, A0l,
                                                    nullptr, nullptr, nullptr, nullptr, nullptr, nullptr);
    // 4. t1 = h @ ew0^T
    mma_gemm<0, 0><<<dim3(8, 32), 256, GEMM_SMEM>>>(A0h, A0l, Wh + 1536 * 512, Wl + 1536 * 512,
                                                    nullptr, t1, 512, 512, nullptr, nullptr, nullptr,
                                                    nullptr, nullptr, nullptr, nullptr, nullptr, nullptr);
    ln_hilo<<<512, 256>>>(t1, g1, b1, A1h, A1l);
    // 5. t3 = h + silu(ln1 @ ew1^T)
    mma_gemm<2, 0><<<dim3(8, 32), 256, GEMM_SMEM>>>(A1h, A1l, Wh + 2048 * 512, Wl + 2048 * 512,
                                                    hb, t3, 512, 512, nullptr, nullptr, nullptr,
                                                    nullptr, nullptr, nullptr, nullptr, nullptr, nullptr);
    ln_hilo<<<512, 256>>>(t3, g2, b2, A0h, A0l);
    // 6. t2 = t3 + silu(ln2 @ ew2^T)
    mma_gemm<2, 0><<<dim3(8, 32), 256, GEMM_SMEM>>>(A0h, A0l, Wh + 2560 * 512, Wl + 2560 * 512,
                                                    t3, t2, 512, 512, nullptr, nullptr, nullptr,
                                                    nullptr, nullptr, nullptr, nullptr, nullptr, nullptr);
    // 7. rms + head
    rms_hilo<<<512, 256>>>(t2, A1h, A1l);
    mma_gemm<3, 0><<<dim3(1, 32), 256, GEMM_SMEM>>>(A1h, A1l, Wh + 3072 * 512, Wl + 3072 * 512,
                                                    nullptr, out, 32, 32, ctemp, nullptr, nullptr,
                                                    nullptr, nullptr, nullptr, nullptr, nullptr, nullptr);
}